// round 4
// baseline (speedup 1.0000x reference)
#include <cuda_runtime.h>
#include <math.h>

#define B_ 2048
#define M_ 64
#define H_ 256
#define E_ 256
#define U_ 1000
#define V_ 50000

// Output buffer layout (f32, concatenated in reference-return order)
static const size_t OUT_OFF  = 0;                               // (B,1,V)
static const size_t HID_OFF  = (size_t)B_ * V_;                 // (1,B,H)
static const size_t EMB_OFF  = HID_OFF + (size_t)B_ * H_;       // (B,1,E)
static const size_t GRU_OFF  = EMB_OFF + (size_t)B_ * E_;       // (B,1,H)
static const size_t ATTN_OFF = GRU_OFF + (size_t)B_ * H_;       // (B,M)

// Scratch (static device arrays; no allocation allowed)
__device__ __align__(16) float g_xcat[(size_t)B_ * 512];  // [emb | context]
__device__ __align__(16) float g_gi[(size_t)B_ * 768];
__device__ __align__(16) float g_gh[(size_t)B_ * 768];

// Dynamic smem floats for attention kernel
#define ATTN_SMEM_FLOATS 36480
#define ATTN_SMEM_BYTES  (ATTN_SMEM_FLOATS * 4)

// ---------------------------------------------------------------------------
// Kernel A: per-batch attention.  One CTA (256 threads) per batch element.
//   io_a   = X(64x256) @ W_inter[u] + b_inter[u]
//   ht_a   = h0 @ W_hidden[u] + b_hidden[u]
//   htpart = ht_a @ W_lt1[u][0:H]
//   energy[m] = sum_k tanh(htpart[k] + (io_a @ W_lt1[u][H:2H])[m,k] + b_lt1[k]) * W_scale[u][k]
//               + b_scale[u]
//   attn = softmax_m(energy); context = attn @ X
//   xcat[b] = [emb[b], context]
// ---------------------------------------------------------------------------
__global__ void __launch_bounds__(256, 1) attn_kernel(
    const float* __restrict__ X_all,     // inter_output (B,M,H)
    const float* __restrict__ hidden,    // (1,B,H)
    const float* __restrict__ emb,       // (B,1,E)
    const float* __restrict__ W_inter, const float* __restrict__ b_inter,
    const float* __restrict__ W_hidden, const float* __restrict__ b_hidden,
    const float* __restrict__ W_scale, const float* __restrict__ b_scale,
    const float* __restrict__ W_lt1, const float* __restrict__ b_lt1,
    const int* __restrict__ user_list,
    float* __restrict__ out_attn,        // (B,M)
    float* __restrict__ xcat)            // (B,512)
{
    extern __shared__ float sm[];
    float* sX   = sm;                 // 64*256 = 16384  X row-major [m][h]
    float* sIo  = sm + 16384;         // 16384           io_a row-major [m][k]
    float* sW   = sm + 32768;         // 8*256 = 2048    streamed weight tile
    float* sH   = sm + 34816;         // 256             h0
    float* sHt  = sm + 35072;         // 256             ht_a
    float* sHtp = sm + 35328;         // 256             htpart
    float* sBi  = sm + 35584;         // 256             b_inter[u]
    float* sBl  = sm + 35840;         // 256             b_lt1[u]
    float* sWs  = sm + 36096;         // 256             W_scale[u]
    float* sE   = sm + 36352;         // 64              energies
    float* sA   = sm + 36416;         // 64              attn weights

    const int b   = blockIdx.x;
    const int tid = threadIdx.x;
    const int u   = user_list[b];
    const int tk  = tid & 31;   // 32 k-groups, each owns k in {tk*4..+3} U {128+tk*4..+3}
    const int tm  = tid >> 5;   // 8 m-groups, each owns m in {tm*8..+7}

    // ---- stage 0: load X, h0, per-user vectors
    {
        const float4* src = (const float4*)(X_all + (size_t)b * (M_ * H_));
        float4* dst = (float4*)sX;
        #pragma unroll
        for (int i = 0; i < 16; ++i) dst[tid + 256 * i] = src[tid + 256 * i];
    }
    sH[tid]  = hidden[(size_t)b * H_ + tid];
    sBi[tid] = b_inter[(size_t)u * H_ + tid];
    sBl[tid] = b_lt1[(size_t)u * H_ + tid];
    sWs[tid] = W_scale[(size_t)u * H_ + tid];
    if (tid < 64) sE[tid] = b_scale[u];
    __syncthreads();

    // ---- stage 1: ht_a[k] (thread = k), coalesced W_hidden reads
    {
        const float* Wh = W_hidden + (size_t)u * H_ * H_;
        float acc = 0.f;
        #pragma unroll 8
        for (int h = 0; h < H_; ++h) acc += sH[h] * Wh[h * H_ + tid];
        sHt[tid] = acc + b_hidden[(size_t)u * H_ + tid];
    }
    __syncthreads();

    // ---- stage 2: htpart[k] = ht_a @ W_lt1[0:H]
    {
        const float* Wl = W_lt1 + (size_t)u * 2 * H_ * H_;
        float acc = 0.f;
        #pragma unroll 8
        for (int h = 0; h < H_; ++h) acc += sHt[h] * Wl[h * H_ + tid];
        sHtp[tid] = acc;
    }

    float acc[8][8];

    // ---- stage 3: io_a = X @ W_inter[u]   (64x256, K=256), W streamed 8 rows/chunk
    #pragma unroll
    for (int mi = 0; mi < 8; ++mi)
        #pragma unroll
        for (int ki = 0; ki < 8; ++ki) acc[mi][ki] = 0.f;
    {
        const float* Wi = W_inter + (size_t)u * H_ * H_;
        for (int h0 = 0; h0 < H_; h0 += 8) {
            __syncthreads();
            {
                const float4* src = (const float4*)(Wi + h0 * H_);
                float4* dst = (float4*)sW;
                dst[tid]       = src[tid];
                dst[tid + 256] = src[tid + 256];
            }
            __syncthreads();
            #pragma unroll
            for (int hh = 0; hh < 8; ++hh) {
                const int h = h0 + hh;
                float4 b0 = *(const float4*)&sW[hh * H_ + tk * 4];
                float4 b1 = *(const float4*)&sW[hh * H_ + 128 + tk * 4];
                float bb[8] = {b0.x, b0.y, b0.z, b0.w, b1.x, b1.y, b1.z, b1.w};
                #pragma unroll
                for (int mi = 0; mi < 8; ++mi) {
                    float a = sX[(tm * 8 + mi) * H_ + h];
                    #pragma unroll
                    for (int ki = 0; ki < 8; ++ki) acc[mi][ki] += a * bb[ki];
                }
            }
        }
    }
    #pragma unroll
    for (int mi = 0; mi < 8; ++mi) {
        #pragma unroll
        for (int ki = 0; ki < 8; ++ki) {
            int k = (ki < 4) ? (tk * 4 + ki) : (128 + tk * 4 + (ki - 4));
            sIo[(tm * 8 + mi) * H_ + k] = acc[mi][ki] + sBi[k];
        }
    }
    // sIo writes complete before next loop's first __syncthreads

    // ---- stage 4: result = tanh(htpart + io_a @ W_lt1[H:2H] + b_lt1); energies fused
    #pragma unroll
    for (int mi = 0; mi < 8; ++mi)
        #pragma unroll
        for (int ki = 0; ki < 8; ++ki) acc[mi][ki] = 0.f;
    {
        const float* Wl2 = W_lt1 + (size_t)u * 2 * H_ * H_ + (size_t)H_ * H_;
        for (int h0 = 0; h0 < H_; h0 += 8) {
            __syncthreads();
            {
                const float4* src = (const float4*)(Wl2 + h0 * H_);
                float4* dst = (float4*)sW;
                dst[tid]       = src[tid];
                dst[tid + 256] = src[tid + 256];
            }
            __syncthreads();
            #pragma unroll
            for (int hh = 0; hh < 8; ++hh) {
                const int h = h0 + hh;
                float4 b0 = *(const float4*)&sW[hh * H_ + tk * 4];
                float4 b1 = *(const float4*)&sW[hh * H_ + 128 + tk * 4];
                float bb[8] = {b0.x, b0.y, b0.z, b0.w, b1.x, b1.y, b1.z, b1.w};
                #pragma unroll
                for (int mi = 0; mi < 8; ++mi) {
                    float a = sIo[(tm * 8 + mi) * H_ + h];
                    #pragma unroll
                    for (int ki = 0; ki < 8; ++ki) acc[mi][ki] += a * bb[ki];
                }
            }
        }
    }
    {
        float ep[8] = {0.f, 0.f, 0.f, 0.f, 0.f, 0.f, 0.f, 0.f};
        #pragma unroll
        for (int ki = 0; ki < 8; ++ki) {
            int k = (ki < 4) ? (tk * 4 + ki) : (128 + tk * 4 + (ki - 4));
            float add = sHtp[k] + sBl[k];
            float ws  = sWs[k];
            #pragma unroll
            for (int mi = 0; mi < 8; ++mi) {
                float v = tanhf(acc[mi][ki] + add);
                ep[mi] += v * ws;
            }
        }
        #pragma unroll
        for (int mi = 0; mi < 8; ++mi) atomicAdd(&sE[tm * 8 + mi], ep[mi]);
    }
    __syncthreads();

    // ---- stage 5: softmax over 64 (warp 0)
    if (tid < 32) {
        float e0 = sE[tid], e1 = sE[tid + 32];
        float mx = fmaxf(e0, e1);
        #pragma unroll
        for (int o = 16; o > 0; o >>= 1) mx = fmaxf(mx, __shfl_xor_sync(0xffffffffu, mx, o));
        float x0 = expf(e0 - mx), x1 = expf(e1 - mx);
        float s = x0 + x1;
        #pragma unroll
        for (int o = 16; o > 0; o >>= 1) s += __shfl_xor_sync(0xffffffffu, s, o);
        float inv = 1.f / s;
        x0 *= inv; x1 *= inv;
        sA[tid] = x0; sA[tid + 32] = x1;
        out_attn[(size_t)b * M_ + tid]      = x0;
        out_attn[(size_t)b * M_ + tid + 32] = x1;
    }
    __syncthreads();

    // ---- stage 6: context[h] = sum_m attn[m]*X[m][h]; build xcat
    {
        float c = 0.f;
        #pragma unroll 8
        for (int m = 0; m < M_; ++m) c += sA[m] * sX[m * H_ + tid];
        xcat[(size_t)b * 512 + 256 + tid] = c;
        xcat[(size_t)b * 512 + tid]       = emb[(size_t)b * E_ + tid];
    }
}

// ---------------------------------------------------------------------------
// Generic GEMM: C[m,n] = bias[n] + sum_k A[m,k] * B[n,k]
// A: M x K row-major, B: N x K row-major. M % 64 == 0, K % 16 == 0.
// CTA tile 64(m) x 128(n), 256 threads, 4x8 per-thread, register-prefetch.
// ---------------------------------------------------------------------------
#define GEMM_SSTORE()                                                   \
    do {                                                                \
        int kq4 = (tid & 3) * 4;                                        \
        sAt[(kq4 + 0) * 64 + a_m] = pa.x;                               \
        sAt[(kq4 + 1) * 64 + a_m] = pa.y;                               \
        sAt[(kq4 + 2) * 64 + a_m] = pa.z;                               \
        sAt[(kq4 + 3) * 64 + a_m] = pa.w;                               \
        sBt[(kq4 + 0) * 128 + bn0] = pb0.x;                             \
        sBt[(kq4 + 1) * 128 + bn0] = pb0.y;                             \
        sBt[(kq4 + 2) * 128 + bn0] = pb0.z;                             \
        sBt[(kq4 + 3) * 128 + bn0] = pb0.w;                             \
        sBt[(kq4 + 0) * 128 + bn1] = pb1.x;                             \
        sBt[(kq4 + 1) * 128 + bn1] = pb1.y;                             \
        sBt[(kq4 + 2) * 128 + bn1] = pb1.z;                             \
        sBt[(kq4 + 3) * 128 + bn1] = pb1.w;                             \
    } while (0)

__global__ void __launch_bounds__(256) gemm_tn_bias(
    const float* __restrict__ A, const float* __restrict__ Bm,
    const float* __restrict__ bias, float* __restrict__ C,
    int Mrows, int N, int K)
{
    __shared__ float sAt[16 * 64];
    __shared__ float sBt[16 * 128];
    const int tid = threadIdx.x;
    const int mb = blockIdx.y * 64;
    const int nb = blockIdx.x * 128;

    const int a_m = tid >> 2;              // 0..63
    const int bn0 = tid >> 2;              // 0..63
    const int bn1 = 64 + (tid >> 2);       // 64..127
    const int nr0 = min(nb + bn0, N - 1);  // clamp (guard on store)
    const int nr1 = min(nb + bn1, N - 1);

    const float* Arow  = A  + (size_t)(mb + a_m) * K + (tid & 3) * 4;
    const float* Brow0 = Bm + (size_t)nr0 * K + (tid & 3) * 4;
    const float* Brow1 = Bm + (size_t)nr1 * K + (tid & 3) * 4;

    float4 pa  = *(const float4*)(Arow);
    float4 pb0 = *(const float4*)(Brow0);
    float4 pb1 = *(const float4*)(Brow1);
    GEMM_SSTORE();
    __syncthreads();

    float acc[4][8];
    #pragma unroll
    for (int mi = 0; mi < 4; ++mi)
        #pragma unroll
        for (int ni = 0; ni < 8; ++ni) acc[mi][ni] = 0.f;

    const int tn  = tid & 15;   // n in {tn*4..+3} U {64+tn*4..+3}
    const int tmg = tid >> 4;   // m in {tmg*4..+3}

    for (int k0 = 16;; k0 += 16) {
        const bool more = (k0 < K);
        if (more) {
            pa  = *(const float4*)(Arow + k0);
            pb0 = *(const float4*)(Brow0 + k0);
            pb1 = *(const float4*)(Brow1 + k0);
        }
        #pragma unroll
        for (int kk = 0; kk < 16; ++kk) {
            float4 av  = *(const float4*)&sAt[kk * 64 + tmg * 4];
            float4 bv0 = *(const float4*)&sBt[kk * 128 + tn * 4];
            float4 bv1 = *(const float4*)&sBt[kk * 128 + 64 + tn * 4];
            float aa[4] = {av.x, av.y, av.z, av.w};
            float bb[8] = {bv0.x, bv0.y, bv0.z, bv0.w, bv1.x, bv1.y, bv1.z, bv1.w};
            #pragma unroll
            for (int mi = 0; mi < 4; ++mi)
                #pragma unroll
                for (int ni = 0; ni < 8; ++ni) acc[mi][ni] += aa[mi] * bb[ni];
        }
        if (!more) break;
        __syncthreads();
        GEMM_SSTORE();
        __syncthreads();
    }

    // epilogue: vectorized stores (N % 4 == 0 for all our calls)
    #pragma unroll
    for (int half = 0; half < 2; ++half) {
        int n0 = nb + half * 64 + tn * 4;
        if (n0 < N) {
            float4 bv;
            bv.x = bias ? bias[n0 + 0] : 0.f;
            bv.y = bias ? bias[n0 + 1] : 0.f;
            bv.z = bias ? bias[n0 + 2] : 0.f;
            bv.w = bias ? bias[n0 + 3] : 0.f;
            #pragma unroll
            for (int mi = 0; mi < 4; ++mi) {
                int m = mb + tmg * 4 + mi;
                float4 v;
                v.x = acc[mi][half * 4 + 0] + bv.x;
                v.y = acc[mi][half * 4 + 1] + bv.y;
                v.z = acc[mi][half * 4 + 2] + bv.z;
                v.w = acc[mi][half * 4 + 3] + bv.w;
                *(float4*)&C[(size_t)m * N + n0] = v;
            }
        }
    }
}

// ---------------------------------------------------------------------------
// GRU gate fusion: h_new = (1-z)*tanh(i_n + r*h_n) + z*h0
// ---------------------------------------------------------------------------
__global__ void gru_gate_kernel(
    const float* __restrict__ gi, const float* __restrict__ gh,
    const float* __restrict__ hidden,
    float* __restrict__ hid_out, float* __restrict__ gru_out)
{
    int idx = blockIdx.x * 256 + threadIdx.x;   // B*H
    int b = idx >> 8, h = idx & 255;
    const float* gib = gi + (size_t)b * 768;
    const float* ghb = gh + (size_t)b * 768;
    float ir = gib[h], iz = gib[256 + h], in_ = gib[512 + h];
    float hr = ghb[h], hz = ghb[256 + h], hn = ghb[512 + h];
    float r = 1.f / (1.f + expf(-(ir + hr)));
    float z = 1.f / (1.f + expf(-(iz + hz)));
    float nc = tanhf(in_ + r * hn);
    float h0 = hidden[idx];
    float hv = (1.f - z) * nc + z * h0;
    hid_out[idx] = hv;
    gru_out[idx] = hv;
}

// ---------------------------------------------------------------------------
extern "C" void kernel_launch(void* const* d_in, const int* in_sizes, int n_in,
                              void* d_out, int out_size)
{
    (void)in_sizes; (void)n_in; (void)out_size;
    const float* emb      = (const float*)d_in[0];
    const float* hidden   = (const float*)d_in[1];
    const float* inter    = (const float*)d_in[2];
    // d_in[3] = delta_t_h (unused)
    const float* W_inter  = (const float*)d_in[4];
    const float* b_inter  = (const float*)d_in[5];
    const float* W_hidden = (const float*)d_in[6];
    const float* b_hidden = (const float*)d_in[7];
    const float* W_scale  = (const float*)d_in[8];
    const float* b_scale  = (const float*)d_in[9];
    const float* W_lt1    = (const float*)d_in[10];
    const float* b_lt1    = (const float*)d_in[11];
    const float* W_ih     = (const float*)d_in[12];
    const float* W_hh     = (const float*)d_in[13];
    const float* b_ih     = (const float*)d_in[14];
    const float* b_hh     = (const float*)d_in[15];
    const float* W_out    = (const float*)d_in[16];
    const float* b_out    = (const float*)d_in[17];
    // d_in[18] = input (unused)
    const int* user_list  = (const int*)d_in[19];
    float* out = (float*)d_out;

    cudaFuncSetAttribute(attn_kernel,
                         cudaFuncAttributeMaxDynamicSharedMemorySize,
                         ATTN_SMEM_BYTES);

    void *p_xcat = nullptr, *p_gi = nullptr, *p_gh = nullptr;
    cudaGetSymbolAddress(&p_xcat, g_xcat);
    cudaGetSymbolAddress(&p_gi, g_gi);
    cudaGetSymbolAddress(&p_gh, g_gh);

    // 1) attention per batch -> attn out + xcat scratch
    attn_kernel<<<B_, 256, ATTN_SMEM_BYTES>>>(
        inter, hidden, emb,
        W_inter, b_inter, W_hidden, b_hidden,
        W_scale, b_scale, W_lt1, b_lt1,
        user_list, out + ATTN_OFF, (float*)p_xcat);

    // 2) gi = xcat @ W_ih^T + b_ih   (2048 x 768, K=512)
    {
        dim3 grid(768 / 128, B_ / 64);
        gemm_tn_bias<<<grid, 256>>>((const float*)p_xcat, W_ih, b_ih,
                                    (float*)p_gi, B_, 768, 512);
    }
    // 3) gh = h0 @ W_hh^T + b_hh     (2048 x 768, K=256)
    {
        dim3 grid(768 / 128, B_ / 64);
        gemm_tn_bias<<<grid, 256>>>(hidden, W_hh, b_hh,
                                    (float*)p_gh, B_, 768, 256);
    }
    // 4) gates -> h_new written into hidden_new and gru_output regions
    gru_gate_kernel<<<(B_ * H_) / 256, 256>>>(
        (const float*)p_gi, (const float*)p_gh, hidden,
        out + HID_OFF, out + GRU_OFF);

    // 5) output = h_new @ W_out^T + b_out   (2048 x 50000, K=256)
    {
        dim3 grid((V_ + 127) / 128, B_ / 64);
        gemm_tn_bias<<<grid, 256>>>(out + HID_OFF, W_out, b_out,
                                    out + OUT_OFF, B_, V_, 256);
    }

    // 6) emb passthrough output
    cudaMemcpyAsync(out + EMB_OFF, emb, (size_t)B_ * E_ * sizeof(float),
                    cudaMemcpyDeviceToDevice, 0);
}

// round 6
// speedup vs baseline: 1.2870x; 1.2870x over previous
#include <cuda_runtime.h>
#include <cuda_bf16.h>
#include <math.h>
#include <stdint.h>

#define B_ 2048
#define M_ 64
#define H_ 256
#define E_ 256
#define U_ 1000
#define V_ 50000
#define VPAD_ 50176   // 392 * 128

// Output buffer layout (f32, concatenated in reference-return order)
static const size_t OUT_OFF  = 0;                               // (B,1,V)
static const size_t HID_OFF  = (size_t)B_ * V_;                 // (1,B,H)
static const size_t EMB_OFF  = HID_OFF + (size_t)B_ * H_;       // (B,1,E)
static const size_t GRU_OFF  = EMB_OFF + (size_t)B_ * E_;       // (B,1,H)
static const size_t ATTN_OFF = GRU_OFF + (size_t)B_ * H_;       // (B,M)

// Scratch (static device arrays; no allocation allowed)
__device__ __align__(16) float g_xcat[(size_t)B_ * 512];
__device__ __align__(16) float g_gi[(size_t)B_ * 768];
__device__ __align__(16) float g_gh[(size_t)B_ * 768];
// split-bf16 operands for the vocab GEMM
__device__ __align__(16) __nv_bfloat16 g_b_hi[(size_t)VPAD_ * H_];
__device__ __align__(16) __nv_bfloat16 g_b_lo[(size_t)VPAD_ * H_];
__device__ __align__(16) __nv_bfloat16 g_a_hi[(size_t)B_ * H_];
__device__ __align__(16) __nv_bfloat16 g_a_lo[(size_t)B_ * H_];

// ===========================================================================
// PTX helpers (family-portable: mma.sync / ldmatrix / cp.async only)
// ===========================================================================
__device__ __forceinline__ uint32_t smem_u32(const void* p) {
    uint32_t a;
    asm("{ .reg .u64 t; cvta.to.shared.u64 t, %1; cvt.u32.u64 %0, t; }" : "=r"(a) : "l"(p));
    return a;
}
#define LDSM4(r0, r1, r2, r3, addr) \
    asm volatile("ldmatrix.sync.aligned.m8n8.x4.shared.b16 {%0,%1,%2,%3}, [%4];" \
        : "=r"(r0), "=r"(r1), "=r"(r2), "=r"(r3) : "r"(addr))
#define MMA_BF16(d, a, b) \
    asm volatile("mma.sync.aligned.m16n8k16.row.col.f32.bf16.bf16.f32 " \
        "{%0,%1,%2,%3}, {%4,%5,%6,%7}, {%8,%9}, {%0,%1,%2,%3};" \
        : "+f"((d)[0]), "+f"((d)[1]), "+f"((d)[2]), "+f"((d)[3]) \
        : "r"((a)[0]), "r"((a)[1]), "r"((a)[2]), "r"((a)[3]), "r"((b)[0]), "r"((b)[1]))
#define CP_ASYNC16(dst, src) \
    asm volatile("cp.async.cg.shared.global [%0], [%1], 16;" :: "r"(dst), "l"(src))
#define CP_COMMIT() asm volatile("cp.async.commit_group;" ::: "memory")
#define CP_WAIT1()  asm volatile("cp.async.wait_group 1;" ::: "memory")
#define CP_WAIT0()  asm volatile("cp.async.wait_group 0;" ::: "memory")

// Dynamic smem floats for attention kernel
#define ATTN_SMEM_FLOATS 36480
#define ATTN_SMEM_BYTES  (ATTN_SMEM_FLOATS * 4)

// ---------------------------------------------------------------------------
// Kernel A: per-batch attention (unchanged, correct since R3).
// ---------------------------------------------------------------------------
__global__ void __launch_bounds__(256, 1) attn_kernel(
    const float* __restrict__ X_all,
    const float* __restrict__ hidden,
    const float* __restrict__ emb,
    const float* __restrict__ W_inter, const float* __restrict__ b_inter,
    const float* __restrict__ W_hidden, const float* __restrict__ b_hidden,
    const float* __restrict__ W_scale, const float* __restrict__ b_scale,
    const float* __restrict__ W_lt1, const float* __restrict__ b_lt1,
    const int* __restrict__ user_list,
    float* __restrict__ out_attn,
    float* __restrict__ xcat)
{
    extern __shared__ float sm[];
    float* sX   = sm;
    float* sIo  = sm + 16384;
    float* sW   = sm + 32768;
    float* sH   = sm + 34816;
    float* sHt  = sm + 35072;
    float* sHtp = sm + 35328;
    float* sBi  = sm + 35584;
    float* sBl  = sm + 35840;
    float* sWs  = sm + 36096;
    float* sE   = sm + 36352;
    float* sA   = sm + 36416;

    const int b   = blockIdx.x;
    const int tid = threadIdx.x;
    const int u   = user_list[b];
    const int tk  = tid & 31;
    const int tm  = tid >> 5;

    {
        const float4* src = (const float4*)(X_all + (size_t)b * (M_ * H_));
        float4* dst = (float4*)sX;
        #pragma unroll
        for (int i = 0; i < 16; ++i) dst[tid + 256 * i] = src[tid + 256 * i];
    }
    sH[tid]  = hidden[(size_t)b * H_ + tid];
    sBi[tid] = b_inter[(size_t)u * H_ + tid];
    sBl[tid] = b_lt1[(size_t)u * H_ + tid];
    sWs[tid] = W_scale[(size_t)u * H_ + tid];
    if (tid < 64) sE[tid] = b_scale[u];
    __syncthreads();

    {
        const float* Wh = W_hidden + (size_t)u * H_ * H_;
        float acc = 0.f;
        #pragma unroll 8
        for (int h = 0; h < H_; ++h) acc += sH[h] * Wh[h * H_ + tid];
        sHt[tid] = acc + b_hidden[(size_t)u * H_ + tid];
    }
    __syncthreads();

    {
        const float* Wl = W_lt1 + (size_t)u * 2 * H_ * H_;
        float acc = 0.f;
        #pragma unroll 8
        for (int h = 0; h < H_; ++h) acc += sHt[h] * Wl[h * H_ + tid];
        sHtp[tid] = acc;
    }

    float acc[8][8];

    #pragma unroll
    for (int mi = 0; mi < 8; ++mi)
        #pragma unroll
        for (int ki = 0; ki < 8; ++ki) acc[mi][ki] = 0.f;
    {
        const float* Wi = W_inter + (size_t)u * H_ * H_;
        for (int h0 = 0; h0 < H_; h0 += 8) {
            __syncthreads();
            {
                const float4* src = (const float4*)(Wi + h0 * H_);
                float4* dst = (float4*)sW;
                dst[tid]       = src[tid];
                dst[tid + 256] = src[tid + 256];
            }
            __syncthreads();
            #pragma unroll
            for (int hh = 0; hh < 8; ++hh) {
                const int h = h0 + hh;
                float4 b0 = *(const float4*)&sW[hh * H_ + tk * 4];
                float4 b1 = *(const float4*)&sW[hh * H_ + 128 + tk * 4];
                float bb[8] = {b0.x, b0.y, b0.z, b0.w, b1.x, b1.y, b1.z, b1.w};
                #pragma unroll
                for (int mi = 0; mi < 8; ++mi) {
                    float a = sX[(tm * 8 + mi) * H_ + h];
                    #pragma unroll
                    for (int ki = 0; ki < 8; ++ki) acc[mi][ki] += a * bb[ki];
                }
            }
        }
    }
    #pragma unroll
    for (int mi = 0; mi < 8; ++mi) {
        #pragma unroll
        for (int ki = 0; ki < 8; ++ki) {
            int k = (ki < 4) ? (tk * 4 + ki) : (128 + tk * 4 + (ki - 4));
            sIo[(tm * 8 + mi) * H_ + k] = acc[mi][ki] + sBi[k];
        }
    }

    #pragma unroll
    for (int mi = 0; mi < 8; ++mi)
        #pragma unroll
        for (int ki = 0; ki < 8; ++ki) acc[mi][ki] = 0.f;
    {
        const float* Wl2 = W_lt1 + (size_t)u * 2 * H_ * H_ + (size_t)H_ * H_;
        for (int h0 = 0; h0 < H_; h0 += 8) {
            __syncthreads();
            {
                const float4* src = (const float4*)(Wl2 + h0 * H_);
                float4* dst = (float4*)sW;
                dst[tid]       = src[tid];
                dst[tid + 256] = src[tid + 256];
            }
            __syncthreads();
            #pragma unroll
            for (int hh = 0; hh < 8; ++hh) {
                const int h = h0 + hh;
                float4 b0 = *(const float4*)&sW[hh * H_ + tk * 4];
                float4 b1 = *(const float4*)&sW[hh * H_ + 128 + tk * 4];
                float bb[8] = {b0.x, b0.y, b0.z, b0.w, b1.x, b1.y, b1.z, b1.w};
                #pragma unroll
                for (int mi = 0; mi < 8; ++mi) {
                    float a = sIo[(tm * 8 + mi) * H_ + h];
                    #pragma unroll
                    for (int ki = 0; ki < 8; ++ki) acc[mi][ki] += a * bb[ki];
                }
            }
        }
    }
    {
        float ep[8] = {0.f, 0.f, 0.f, 0.f, 0.f, 0.f, 0.f, 0.f};
        #pragma unroll
        for (int ki = 0; ki < 8; ++ki) {
            int k = (ki < 4) ? (tk * 4 + ki) : (128 + tk * 4 + (ki - 4));
            float add = sHtp[k] + sBl[k];
            float ws  = sWs[k];
            #pragma unroll
            for (int mi = 0; mi < 8; ++mi) {
                float v = tanhf(acc[mi][ki] + add);
                ep[mi] += v * ws;
            }
        }
        #pragma unroll
        for (int mi = 0; mi < 8; ++mi) atomicAdd(&sE[tm * 8 + mi], ep[mi]);
    }
    __syncthreads();

    if (tid < 32) {
        float e0 = sE[tid], e1 = sE[tid + 32];
        float mx = fmaxf(e0, e1);
        #pragma unroll
        for (int o = 16; o > 0; o >>= 1) mx = fmaxf(mx, __shfl_xor_sync(0xffffffffu, mx, o));
        float x0 = expf(e0 - mx), x1 = expf(e1 - mx);
        float s = x0 + x1;
        #pragma unroll
        for (int o = 16; o > 0; o >>= 1) s += __shfl_xor_sync(0xffffffffu, s, o);
        float inv = 1.f / s;
        x0 *= inv; x1 *= inv;
        sA[tid] = x0; sA[tid + 32] = x1;
        out_attn[(size_t)b * M_ + tid]      = x0;
        out_attn[(size_t)b * M_ + tid + 32] = x1;
    }
    __syncthreads();

    {
        float c = 0.f;
        #pragma unroll 8
        for (int m = 0; m < M_; ++m) c += sA[m] * sX[m * H_ + tid];
        xcat[(size_t)b * 512 + 256 + tid] = c;
        xcat[(size_t)b * 512 + tid]       = emb[(size_t)b * E_ + tid];
    }
}

// ---------------------------------------------------------------------------
// Generic SIMT GEMM (gi/gh): C[m,n] = bias[n] + sum_k A[m,k]*B[n,k]
// ---------------------------------------------------------------------------
#define GEMM_SSTORE()                                                   \
    do {                                                                \
        int kq4 = (tid & 3) * 4;                                        \
        sAt[(kq4 + 0) * 64 + a_m] = pa.x;                               \
        sAt[(kq4 + 1) * 64 + a_m] = pa.y;                               \
        sAt[(kq4 + 2) * 64 + a_m] = pa.z;                               \
        sAt[(kq4 + 3) * 64 + a_m] = pa.w;                               \
        sBt[(kq4 + 0) * 128 + bn0] = pb0.x;                             \
        sBt[(kq4 + 1) * 128 + bn0] = pb0.y;                             \
        sBt[(kq4 + 2) * 128 + bn0] = pb0.z;                             \
        sBt[(kq4 + 3) * 128 + bn0] = pb0.w;                             \
        sBt[(kq4 + 0) * 128 + bn1] = pb1.x;                             \
        sBt[(kq4 + 1) * 128 + bn1] = pb1.y;                             \
        sBt[(kq4 + 2) * 128 + bn1] = pb1.z;                             \
        sBt[(kq4 + 3) * 128 + bn1] = pb1.w;                             \
    } while (0)

__global__ void __launch_bounds__(256) gemm_tn_bias(
    const float* __restrict__ A, const float* __restrict__ Bm,
    const float* __restrict__ bias, float* __restrict__ C,
    int Mrows, int N, int K)
{
    __shared__ float sAt[16 * 64];
    __shared__ float sBt[16 * 128];
    const int tid = threadIdx.x;
    const int mb = blockIdx.y * 64;
    const int nb = blockIdx.x * 128;

    const int a_m = tid >> 2;
    const int bn0 = tid >> 2;
    const int bn1 = 64 + (tid >> 2);
    const int nr0 = min(nb + bn0, N - 1);
    const int nr1 = min(nb + bn1, N - 1);

    const float* Arow  = A  + (size_t)(mb + a_m) * K + (tid & 3) * 4;
    const float* Brow0 = Bm + (size_t)nr0 * K + (tid & 3) * 4;
    const float* Brow1 = Bm + (size_t)nr1 * K + (tid & 3) * 4;

    float4 pa  = *(const float4*)(Arow);
    float4 pb0 = *(const float4*)(Brow0);
    float4 pb1 = *(const float4*)(Brow1);
    GEMM_SSTORE();
    __syncthreads();

    float acc[4][8];
    #pragma unroll
    for (int mi = 0; mi < 4; ++mi)
        #pragma unroll
        for (int ni = 0; ni < 8; ++ni) acc[mi][ni] = 0.f;

    const int tn  = tid & 15;
    const int tmg = tid >> 4;

    for (int k0 = 16;; k0 += 16) {
        const bool more = (k0 < K);
        if (more) {
            pa  = *(const float4*)(Arow + k0);
            pb0 = *(const float4*)(Brow0 + k0);
            pb1 = *(const float4*)(Brow1 + k0);
        }
        #pragma unroll
        for (int kk = 0; kk < 16; ++kk) {
            float4 av  = *(const float4*)&sAt[kk * 64 + tmg * 4];
            float4 bv0 = *(const float4*)&sBt[kk * 128 + tn * 4];
            float4 bv1 = *(const float4*)&sBt[kk * 128 + 64 + tn * 4];
            float aa[4] = {av.x, av.y, av.z, av.w};
            float bb[8] = {bv0.x, bv0.y, bv0.z, bv0.w, bv1.x, bv1.y, bv1.z, bv1.w};
            #pragma unroll
            for (int mi = 0; mi < 4; ++mi)
                #pragma unroll
                for (int ni = 0; ni < 8; ++ni) acc[mi][ni] += aa[mi] * bb[ni];
        }
        if (!more) break;
        __syncthreads();
        GEMM_SSTORE();
        __syncthreads();
    }

    #pragma unroll
    for (int half = 0; half < 2; ++half) {
        int n0 = nb + half * 64 + tn * 4;
        if (n0 < N) {
            float4 bv;
            bv.x = bias ? bias[n0 + 0] : 0.f;
            bv.y = bias ? bias[n0 + 1] : 0.f;
            bv.z = bias ? bias[n0 + 2] : 0.f;
            bv.w = bias ? bias[n0 + 3] : 0.f;
            #pragma unroll
            for (int mi = 0; mi < 4; ++mi) {
                int m = mb + tmg * 4 + mi;
                float4 v;
                v.x = acc[mi][half * 4 + 0] + bv.x;
                v.y = acc[mi][half * 4 + 1] + bv.y;
                v.z = acc[mi][half * 4 + 2] + bv.z;
                v.w = acc[mi][half * 4 + 3] + bv.w;
                *(float4*)&C[(size_t)m * N + n0] = v;
            }
        }
    }
}

// ---------------------------------------------------------------------------
// GRU gate fusion
// ---------------------------------------------------------------------------
__global__ void gru_gate_kernel(
    const float* __restrict__ gi, const float* __restrict__ gh,
    const float* __restrict__ hidden,
    float* __restrict__ hid_out, float* __restrict__ gru_out)
{
    int idx = blockIdx.x * 256 + threadIdx.x;
    int b = idx >> 8, h = idx & 255;
    const float* gib = gi + (size_t)b * 768;
    const float* ghb = gh + (size_t)b * 768;
    float ir = gib[h], iz = gib[256 + h], in_ = gib[512 + h];
    float hr = ghb[h], hz = ghb[256 + h], hn = ghb[512 + h];
    float r = 1.f / (1.f + expf(-(ir + hr)));
    float z = 1.f / (1.f + expf(-(iz + hz)));
    float nc = tanhf(in_ + r * hn);
    float h0 = hidden[idx];
    float hv = (1.f - z) * nc + z * h0;
    hid_out[idx] = hv;
    gru_out[idx] = hv;
}

// ---------------------------------------------------------------------------
// Split-bf16 conversion kernels
// ---------------------------------------------------------------------------
__global__ void cvt_b_kernel(const float* __restrict__ W,
                             __nv_bfloat16* __restrict__ hi,
                             __nv_bfloat16* __restrict__ lo)
{
    size_t r = blockIdx.x;
    int c = threadIdx.x;
    size_t i = r * H_ + c;
    float v = (r < V_) ? W[i] : 0.f;
    __nv_bfloat16 h = __float2bfloat16(v);
    float res = v - __bfloat162float(h);
    hi[i] = h;
    lo[i] = __float2bfloat16(res);
}

__global__ void cvt_a_kernel(const float* __restrict__ A,
                             __nv_bfloat16* __restrict__ hi,
                             __nv_bfloat16* __restrict__ lo)
{
    size_t i = (size_t)blockIdx.x * 256 + threadIdx.x;
    float v = A[i];
    __nv_bfloat16 h = __float2bfloat16(v);
    float res = v - __bfloat162float(h);
    hi[i] = h;
    lo[i] = __float2bfloat16(res);
}

// ---------------------------------------------------------------------------
// mma.sync vocab GEMM: C[2048, 50000] = A[2048,256] @ B[50000,256]^T + bias
// split-bf16 (hi+lo, 3 terms), f32 accumulate in registers.
// CTA tile 128x128, K chunked by 64, cp.async 2-stage pipeline.
// 8 warps in 2(m) x 4(n); warp tile 64x32; m16n8k16 fragments via ldmatrix.
// Smem tiles padded to 72 bf16 (144 B) rows for conflict-free ldmatrix.
// ---------------------------------------------------------------------------
#define VROW 144u                  // bytes per smem tile row (64*2 + 16 pad)
#define VTILE_BYTES (128u * VROW)  // 18432
#define VSTAGE_BYTES (4u * VTILE_BYTES)       // A_hi A_lo B_hi B_lo = 73728
#define VSMEM_BYTES  (2u * VSTAGE_BYTES)      // 147456

#define VOFF_AHI 0u
#define VOFF_ALO VTILE_BYTES
#define VOFF_BHI (2u * VTILE_BYTES)
#define VOFF_BLO (3u * VTILE_BYTES)

__device__ __forceinline__ void v_load_chunk(
    uint32_t sbase,
    const __nv_bfloat16* __restrict__ Ahi, const __nv_bfloat16* __restrict__ Alo,
    const __nv_bfloat16* __restrict__ Bhi, const __nv_bfloat16* __restrict__ Blo,
    size_t mb, size_t nb, int kc, int tid)
{
    const size_t koff = (size_t)kc * 64;
    #pragma unroll
    for (int it = 0; it < 4; ++it) {
        int idx = tid + it * 256;          // 0..1023
        int r = idx >> 3, c = idx & 7;
        uint32_t soff = (uint32_t)r * VROW + (uint32_t)c * 16u;
        const __nv_bfloat16* ga = Ahi + (mb + r) * H_ + koff + c * 8;
        CP_ASYNC16(sbase + VOFF_AHI + soff, ga);
        const __nv_bfloat16* ga2 = Alo + (mb + r) * H_ + koff + c * 8;
        CP_ASYNC16(sbase + VOFF_ALO + soff, ga2);
        const __nv_bfloat16* gb = Bhi + (nb + r) * H_ + koff + c * 8;
        CP_ASYNC16(sbase + VOFF_BHI + soff, gb);
        const __nv_bfloat16* gb2 = Blo + (nb + r) * H_ + koff + c * 8;
        CP_ASYNC16(sbase + VOFF_BLO + soff, gb2);
    }
}

__global__ void __launch_bounds__(256, 1) vocab_mma_kernel(
    const __nv_bfloat16* __restrict__ Ahi, const __nv_bfloat16* __restrict__ Alo,
    const __nv_bfloat16* __restrict__ Bhi, const __nv_bfloat16* __restrict__ Blo,
    const float* __restrict__ bias, float* __restrict__ C)
{
    extern __shared__ char smraw[];
    const uint32_t smb = smem_u32(smraw);

    const int tid  = threadIdx.x;
    const int wid  = tid >> 5;
    const int lane = tid & 31;
    const int wm   = wid & 1;          // 0..1  (m 64-halves)
    const int wn   = wid >> 1;         // 0..3  (n 32-quarters)
    const size_t mb = (size_t)blockIdx.x * 128;
    const size_t nb = (size_t)blockIdx.y * 128;

    const int lr = lane & 7;           // ldmatrix row-within-8x8
    const int lg = lane >> 3;          // ldmatrix group 0..3

    // Per-lane smem row/col offsets for ldmatrix (independent of stage/kstep)
    // A tile (mt): row = wm*64 + mt*16 + lr + (lg&1)*8 ; kbyte = (lg>>1)*16
    // B tile (pair p): row = wn*32 + p*16 + lr + (lg>>1)*8 ; kbyte = (lg&1)*16
    uint32_t aRow[4], bRow[2];
    #pragma unroll
    for (int mt = 0; mt < 4; ++mt)
        aRow[mt] = (uint32_t)(wm * 64 + mt * 16 + lr + (lg & 1) * 8) * VROW
                 + (uint32_t)((lg >> 1) * 16);
    #pragma unroll
    for (int p = 0; p < 2; ++p)
        bRow[p] = (uint32_t)(wn * 32 + p * 16 + lr + (lg >> 1) * 8) * VROW
                + (uint32_t)((lg & 1) * 16);

    float acc[4][4][4];
    #pragma unroll
    for (int mt = 0; mt < 4; ++mt)
        #pragma unroll
        for (int nt = 0; nt < 4; ++nt)
            #pragma unroll
            for (int i = 0; i < 4; ++i) acc[mt][nt][i] = 0.f;

    // Prologue: load chunk 0 into stage 0
    v_load_chunk(smb, Ahi, Alo, Bhi, Blo, mb, nb, 0, tid);
    CP_COMMIT();

    for (int ch = 0; ch < 4; ++ch) {
        const uint32_t st = (uint32_t)(ch & 1) * VSTAGE_BYTES;
        if (ch < 3) {
            v_load_chunk(smb + ((uint32_t)((ch + 1) & 1) * VSTAGE_BYTES),
                         Ahi, Alo, Bhi, Blo, mb, nb, ch + 1, tid);
            CP_COMMIT();
            CP_WAIT1();
        } else {
            CP_WAIT0();
        }
        __syncthreads();

        const uint32_t aHiB = smb + st + VOFF_AHI;
        const uint32_t aLoB = smb + st + VOFF_ALO;
        const uint32_t bHiB = smb + st + VOFF_BHI;
        const uint32_t bLoB = smb + st + VOFF_BLO;

        #pragma unroll
        for (int ks = 0; ks < 4; ++ks) {
            const uint32_t kso = (uint32_t)ks * 32u;  // 16 bf16 = 32 bytes
            uint32_t ah[4][4], al[4][4];
            #pragma unroll
            for (int mt = 0; mt < 4; ++mt) {
                LDSM4(ah[mt][0], ah[mt][1], ah[mt][2], ah[mt][3], aHiB + aRow[mt] + kso);
                LDSM4(al[mt][0], al[mt][1], al[mt][2], al[mt][3], aLoB + aRow[mt] + kso);
            }
            uint32_t bh[4][2], bl[4][2];
            #pragma unroll
            for (int p = 0; p < 2; ++p) {
                LDSM4(bh[2 * p][0], bh[2 * p][1], bh[2 * p + 1][0], bh[2 * p + 1][1],
                      bHiB + bRow[p] + kso);
                LDSM4(bl[2 * p][0], bl[2 * p][1], bl[2 * p + 1][0], bl[2 * p + 1][1],
                      bLoB + bRow[p] + kso);
            }
            #pragma unroll
            for (int mt = 0; mt < 4; ++mt)
                #pragma unroll
                for (int nt = 0; nt < 4; ++nt) {
                    MMA_BF16(acc[mt][nt], ah[mt], bh[nt]);
                    MMA_BF16(acc[mt][nt], ah[mt], bl[nt]);
                    MMA_BF16(acc[mt][nt], al[mt], bh[nt]);
                }
        }
        __syncthreads();
    }

    // Epilogue: direct stores with bias.  Thread (lane) owns rows lane/4 (+8),
    // cols (lane%4)*2 (+1) within each 16x8 mma tile.
    const int rq = lane >> 2, cq = (lane & 3) * 2;
    #pragma unroll
    for (int nt = 0; nt < 4; ++nt) {
        const size_t col = nb + (size_t)wn * 32 + nt * 8 + cq;
        if (col < (size_t)V_) {
            const float2 bv = *(const float2*)&bias[col];
            #pragma unroll
            for (int mt = 0; mt < 4; ++mt) {
                const size_t row0 = mb + (size_t)wm * 64 + mt * 16 + rq;
                float2 v0, v1;
                v0.x = acc[mt][nt][0] + bv.x;
                v0.y = acc[mt][nt][1] + bv.y;
                v1.x = acc[mt][nt][2] + bv.x;
                v1.y = acc[mt][nt][3] + bv.y;
                *(float2*)&C[row0 * V_ + col]       = v0;
                *(float2*)&C[(row0 + 8) * V_ + col] = v1;
            }
        }
    }
}

// ---------------------------------------------------------------------------
extern "C" void kernel_launch(void* const* d_in, const int* in_sizes, int n_in,
                              void* d_out, int out_size)
{
    (void)in_sizes; (void)n_in; (void)out_size;
    const float* emb      = (const float*)d_in[0];
    const float* hidden   = (const float*)d_in[1];
    const float* inter    = (const float*)d_in[2];
    const float* W_inter  = (const float*)d_in[4];
    const float* b_inter  = (const float*)d_in[5];
    const float* W_hidden = (const float*)d_in[6];
    const float* b_hidden = (const float*)d_in[7];
    const float* W_scale  = (const float*)d_in[8];
    const float* b_scale  = (const float*)d_in[9];
    const float* W_lt1    = (const float*)d_in[10];
    const float* b_lt1    = (const float*)d_in[11];
    const float* W_ih     = (const float*)d_in[12];
    const float* W_hh     = (const float*)d_in[13];
    const float* b_ih     = (const float*)d_in[14];
    const float* b_hh     = (const float*)d_in[15];
    const float* W_out    = (const float*)d_in[16];
    const float* b_out    = (const float*)d_in[17];
    const int* user_list  = (const int*)d_in[19];
    float* out = (float*)d_out;

    cudaFuncSetAttribute(attn_kernel,
                         cudaFuncAttributeMaxDynamicSharedMemorySize,
                         ATTN_SMEM_BYTES);
    cudaFuncSetAttribute(vocab_mma_kernel,
                         cudaFuncAttributeMaxDynamicSharedMemorySize,
                         VSMEM_BYTES);

    void *p_xcat = nullptr, *p_gi = nullptr, *p_gh = nullptr;
    void *p_bhi = nullptr, *p_blo = nullptr, *p_ahi = nullptr, *p_alo = nullptr;
    cudaGetSymbolAddress(&p_xcat, g_xcat);
    cudaGetSymbolAddress(&p_gi, g_gi);
    cudaGetSymbolAddress(&p_gh, g_gh);
    cudaGetSymbolAddress(&p_bhi, g_b_hi);
    cudaGetSymbolAddress(&p_blo, g_b_lo);
    cudaGetSymbolAddress(&p_ahi, g_a_hi);
    cudaGetSymbolAddress(&p_alo, g_a_lo);

    // 0) W_out -> split bf16 (padded to VPAD_ rows)
    cvt_b_kernel<<<VPAD_, 256>>>(W_out, (__nv_bfloat16*)p_bhi, (__nv_bfloat16*)p_blo);

    // 1) attention per batch -> attn out + xcat scratch
    attn_kernel<<<B_, 256, ATTN_SMEM_BYTES>>>(
        inter, hidden, emb,
        W_inter, b_inter, W_hidden, b_hidden,
        W_scale, b_scale, W_lt1, b_lt1,
        user_list, out + ATTN_OFF, (float*)p_xcat);

    // 2) gi = xcat @ W_ih^T + b_ih
    {
        dim3 grid(768 / 128, B_ / 64);
        gemm_tn_bias<<<grid, 256>>>((const float*)p_xcat, W_ih, b_ih,
                                    (float*)p_gi, B_, 768, 512);
    }
    // 3) gh = h0 @ W_hh^T + b_hh
    {
        dim3 grid(768 / 128, B_ / 64);
        gemm_tn_bias<<<grid, 256>>>(hidden, W_hh, b_hh,
                                    (float*)p_gh, B_, 768, 256);
    }
    // 4) gates -> h_new
    gru_gate_kernel<<<(B_ * H_) / 256, 256>>>(
        (const float*)p_gi, (const float*)p_gh, hidden,
        out + HID_OFF, out + GRU_OFF);

    // 5) h_new -> split bf16
    cvt_a_kernel<<<(B_ * H_) / 256, 256>>>(out + HID_OFF,
                                           (__nv_bfloat16*)p_ahi,
                                           (__nv_bfloat16*)p_alo);

    // 6) output = h_new @ W_out^T + b_out  (mma.sync split-bf16)
    {
        dim3 grid(B_ / 128, VPAD_ / 128);   // (16 m-fast, 392 n)
        vocab_mma_kernel<<<grid, 256, VSMEM_BYTES>>>(
            (const __nv_bfloat16*)p_ahi, (const __nv_bfloat16*)p_alo,
            (const __nv_bfloat16*)p_bhi, (const __nv_bfloat16*)p_blo,
            b_out, out + OUT_OFF);
    }

    // 7) emb passthrough output
    cudaMemcpyAsync(out + EMB_OFF, emb, (size_t)B_ * E_ * sizeof(float),
                    cudaMemcpyDeviceToDevice, 0);
}

// round 7
// speedup vs baseline: 2.5292x; 1.9652x over previous
#include <cuda_runtime.h>
#include <cuda_bf16.h>
#include <math.h>
#include <stdint.h>

#define B_ 2048
#define M_ 64
#define H_ 256
#define E_ 256
#define U_ 1000
#define V_ 50000
#define VPAD_ 50176   // 392 * 128

// Output buffer layout (f32, concatenated in reference-return order)
static const size_t OUT_OFF  = 0;                               // (B,1,V)
static const size_t HID_OFF  = (size_t)B_ * V_;                 // (1,B,H)
static const size_t EMB_OFF  = HID_OFF + (size_t)B_ * H_;       // (B,1,E)
static const size_t GRU_OFF  = EMB_OFF + (size_t)B_ * E_;       // (B,1,H)
static const size_t ATTN_OFF = GRU_OFF + (size_t)B_ * H_;       // (B,M)

// Scratch (static device arrays; no allocation allowed)
__device__ __align__(16) float g_xcat[(size_t)B_ * 512];
__device__ __align__(16) float g_gi[(size_t)B_ * 768];
__device__ __align__(16) float g_gh[(size_t)B_ * 768];
__device__ int g_perm[B_];
// split-bf16 operands for the vocab GEMM
__device__ __align__(16) __nv_bfloat16 g_b_hi[(size_t)VPAD_ * H_];
__device__ __align__(16) __nv_bfloat16 g_b_lo[(size_t)VPAD_ * H_];
__device__ __align__(16) __nv_bfloat16 g_a_hi[(size_t)B_ * H_];
__device__ __align__(16) __nv_bfloat16 g_a_lo[(size_t)B_ * H_];

// ===========================================================================
// PTX helpers (family-portable: mma.sync / ldmatrix / cp.async only)
// ===========================================================================
__device__ __forceinline__ uint32_t smem_u32(const void* p) {
    uint32_t a;
    asm("{ .reg .u64 t; cvta.to.shared.u64 t, %1; cvt.u32.u64 %0, t; }" : "=r"(a) : "l"(p));
    return a;
}
#define LDSM4(r0, r1, r2, r3, addr) \
    asm volatile("ldmatrix.sync.aligned.m8n8.x4.shared.b16 {%0,%1,%2,%3}, [%4];" \
        : "=r"(r0), "=r"(r1), "=r"(r2), "=r"(r3) : "r"(addr))
#define LDSM4T(r0, r1, r2, r3, addr) \
    asm volatile("ldmatrix.sync.aligned.m8n8.x4.trans.shared.b16 {%0,%1,%2,%3}, [%4];" \
        : "=r"(r0), "=r"(r1), "=r"(r2), "=r"(r3) : "r"(addr))
#define MMA_BF16(d, a, b) \
    asm volatile("mma.sync.aligned.m16n8k16.row.col.f32.bf16.bf16.f32 " \
        "{%0,%1,%2,%3}, {%4,%5,%6,%7}, {%8,%9}, {%0,%1,%2,%3};" \
        : "+f"((d)[0]), "+f"((d)[1]), "+f"((d)[2]), "+f"((d)[3]) \
        : "r"((a)[0]), "r"((a)[1]), "r"((a)[2]), "r"((a)[3]), "r"((b)[0]), "r"((b)[1]))
#define CP_ASYNC16(dst, src) \
    asm volatile("cp.async.cg.shared.global [%0], [%1], 16;" :: "r"(dst), "l"(src))
#define CP_COMMIT() asm volatile("cp.async.commit_group;" ::: "memory")
#define CP_WAIT1()  asm volatile("cp.async.wait_group 1;" ::: "memory")
#define CP_WAIT0()  asm volatile("cp.async.wait_group 0;" ::: "memory")

// ---------------------------------------------------------------------------
// User counting sort: perm orders batches by user so co-resident CTAs share
// gathered weights in L2.  Output of the whole pipeline is independent of the
// CTA->batch mapping, so atomic ordering here does not affect results.
// ---------------------------------------------------------------------------
__global__ void __launch_bounds__(1024) sort_users_kernel(
    const int* __restrict__ ul, int* __restrict__ perm)
{
    __shared__ int hist[1024];
    __shared__ int wsums[32];
    const int tid = threadIdx.x;
    hist[tid] = 0;
    __syncthreads();
    atomicAdd(&hist[ul[tid]], 1);
    atomicAdd(&hist[ul[tid + 1024]], 1);
    __syncthreads();
    int c = hist[tid];
    int v = c;
    #pragma unroll
    for (int o = 1; o < 32; o <<= 1) {
        int t = __shfl_up_sync(0xffffffffu, v, o);
        if ((tid & 31) >= o) v += t;
    }
    if ((tid & 31) == 31) wsums[tid >> 5] = v;
    __syncthreads();
    if (tid < 32) {
        int w = wsums[tid];
        #pragma unroll
        for (int o = 1; o < 32; o <<= 1) {
            int t = __shfl_up_sync(0xffffffffu, w, o);
            if (tid >= o) w += t;
        }
        wsums[tid] = w;
    }
    __syncthreads();
    int excl = v - c + ((tid >= 32) ? wsums[(tid >> 5) - 1] : 0);
    __syncthreads();
    hist[tid] = excl;
    __syncthreads();
    { int b = tid;        perm[atomicAdd(&hist[ul[b]], 1)] = b; }
    { int b = tid + 1024; perm[atomicAdd(&hist[ul[b]], 1)] = b; }
}

// ===========================================================================
// Tensor-core attention kernel.  One CTA (256 thr, 8 warps) per batch.
// GEMM1: io_a = X(64x256) @ W_inter[u]  (split-bf16, 3-term)
// GEMM2: pre-tanh = io_a @ W_lt1[u][H:2H]
// Fused: ht_a / htpart vectors, tanh+W_scale energies, softmax, context.
// smem byte layout (pitch 528B per 256-col bf16 row):
// ===========================================================================
#define PITCH 528u
#define AT_XHI  0u
#define AT_XLO  33792u
#define AT_IOHI 67584u
#define AT_IOLO 101376u
#define AT_WHI  135168u          // 32 rows x 528
#define AT_WLO  152064u
#define AT_FLT  168960u          // float region
#define AT_BYTES 175616u
// float region offsets (bytes from AT_FLT)
#define F_H    0u
#define F_HT   1024u
#define F_HTP  2048u
#define F_BI   3072u
#define F_BL   4096u
#define F_WS   5120u
#define F_E    6144u
#define F_A    6400u

__device__ __forceinline__ void w_ldg32(float2 (&pf)[16],
                                        const float* __restrict__ src,
                                        int h0, int tid)
{
    #pragma unroll
    for (int i = 0; i < 16; ++i) {
        int p = tid + i * 256;
        int hl = p >> 7, n2 = p & 127;
        pf[i] = *(const float2*)(src + (size_t)(h0 + hl) * 256 + n2 * 2);
    }
}

__device__ __forceinline__ void w_store32(const float2 (&pf)[16], char* smb,
                                          uint32_t offHi, uint32_t offLo, int tid)
{
    #pragma unroll
    for (int i = 0; i < 16; ++i) {
        int p = tid + i * 256;
        int hl = p >> 7, n2 = p & 127;
        float x = pf[i].x, y = pf[i].y;
        __nv_bfloat16 hx = __float2bfloat16(x), hy = __float2bfloat16(y);
        __nv_bfloat16 lx = __float2bfloat16(x - __bfloat162float(hx));
        __nv_bfloat16 ly = __float2bfloat16(y - __bfloat162float(hy));
        uint32_t off = (uint32_t)hl * PITCH + (uint32_t)n2 * 4u;
        __nv_bfloat162 vh; vh.x = hx; vh.y = hy;
        __nv_bfloat162 vl; vl.x = lx; vl.y = ly;
        *(__nv_bfloat162*)(smb + offHi + off) = vh;
        *(__nv_bfloat162*)(smb + offLo + off) = vl;
    }
}

__device__ __forceinline__ void mma_chunk32(
    float (&acc)[4][4][4],
    uint32_t aHi, uint32_t aLo, uint32_t aKByte,
    uint32_t wHi, uint32_t wLo, int lane, int wid)
{
    const int lr = lane & 7, lg = lane >> 3;
    const int bkr = (lane & 7) + 8 * ((lane >> 3) & 1);
    const uint32_t bnb = (uint32_t)(wid * 64 + 16 * (lane >> 4));
    #pragma unroll
    for (int ks = 0; ks < 2; ++ks) {
        const uint32_t akb = aKByte + (uint32_t)ks * 32u;
        uint32_t ah[4][4], al[4][4];
        #pragma unroll
        for (int mt = 0; mt < 4; ++mt) {
            uint32_t ar = (uint32_t)(mt * 16 + lr + (lg & 1) * 8) * PITCH
                        + (uint32_t)((lg >> 1) * 16) + akb;
            LDSM4(ah[mt][0], ah[mt][1], ah[mt][2], ah[mt][3], aHi + ar);
            LDSM4(al[mt][0], al[mt][1], al[mt][2], al[mt][3], aLo + ar);
        }
        uint32_t bh[2][4], bl[2][4];
        #pragma unroll
        for (int p = 0; p < 2; ++p) {
            uint32_t br = (uint32_t)(ks * 16 + bkr) * PITCH + bnb + (uint32_t)p * 32u;
            LDSM4T(bh[p][0], bh[p][1], bh[p][2], bh[p][3], wHi + br);
            LDSM4T(bl[p][0], bl[p][1], bl[p][2], bl[p][3], wLo + br);
        }
        #pragma unroll
        for (int mt = 0; mt < 4; ++mt)
            #pragma unroll
            for (int nt = 0; nt < 4; ++nt) {
                const uint32_t* bhp = &bh[nt >> 1][(nt & 1) * 2];
                const uint32_t* blp = &bl[nt >> 1][(nt & 1) * 2];
                MMA_BF16(acc[mt][nt], ah[mt], bhp);
                MMA_BF16(acc[mt][nt], ah[mt], blp);
                MMA_BF16(acc[mt][nt], al[mt], bhp);
            }
    }
}

__global__ void __launch_bounds__(256, 1) attn_mma_kernel(
    const float* __restrict__ X_all,
    const float* __restrict__ hidden,
    const float* __restrict__ emb,
    const float* __restrict__ W_inter, const float* __restrict__ b_inter,
    const float* __restrict__ W_hidden, const float* __restrict__ b_hidden,
    const float* __restrict__ W_scale, const float* __restrict__ b_scale,
    const float* __restrict__ W_lt1, const float* __restrict__ b_lt1,
    const int* __restrict__ user_list,
    const int* __restrict__ perm,
    float* __restrict__ out_attn,
    float* __restrict__ xcat)
{
    extern __shared__ char smraw[];
    char* smb = smraw;
    const uint32_t sma = smem_u32(smraw);
    float* sFlt = (float*)(smb + AT_FLT);
    float* sH   = sFlt + 0;
    float* sHt  = sFlt + 256;
    float* sHtp = sFlt + 512;
    float* sBi  = sFlt + 768;
    float* sBl  = sFlt + 1024;
    float* sWs  = sFlt + 1280;
    float* sE   = sFlt + 1536;
    float* sA   = sFlt + 1600;

    const int tid  = threadIdx.x;
    const int lane = tid & 31;
    const int wid  = tid >> 5;
    const int b    = perm[blockIdx.x];
    const int u    = user_list[b];

    const float* Wi   = W_inter + (size_t)u * 65536;
    const float* Wl1b = W_lt1 + (size_t)u * 131072 + 65536;

    // ---- stage 0: X -> bf16 hi/lo tiles; vectors
    {
        const float* Xg = X_all + (size_t)b * (M_ * H_);
        #pragma unroll
        for (int i = 0; i < 32; ++i) {
            int p = tid + i * 256;
            int m = p >> 7, n2 = p & 127;
            float2 v = *(const float2*)(Xg + m * 256 + n2 * 2);
            __nv_bfloat16 hx = __float2bfloat16(v.x), hy = __float2bfloat16(v.y);
            __nv_bfloat16 lx = __float2bfloat16(v.x - __bfloat162float(hx));
            __nv_bfloat16 ly = __float2bfloat16(v.y - __bfloat162float(hy));
            uint32_t off = (uint32_t)m * PITCH + (uint32_t)n2 * 4u;
            __nv_bfloat162 vh; vh.x = hx; vh.y = hy;
            __nv_bfloat162 vl; vl.x = lx; vl.y = ly;
            *(__nv_bfloat162*)(smb + AT_XHI + off) = vh;
            *(__nv_bfloat162*)(smb + AT_XLO + off) = vl;
        }
    }
    sH[tid]  = hidden[(size_t)b * H_ + tid];
    sBi[tid] = b_inter[(size_t)u * H_ + tid];
    sBl[tid] = b_lt1[(size_t)u * H_ + tid];
    sWs[tid] = W_scale[(size_t)u * H_ + tid];
    if (tid < 64) sE[tid] = b_scale[u];
    __syncthreads();

    float2 pf[16];
    // prefetch GEMM1 chunk 0 early; latency hidden behind vector stages
    w_ldg32(pf, Wi, 0, tid);

    // ---- stage 1: ht_a[k] = h0 @ W_hidden[u] + b_hidden[u]
    {
        const float* Wh = W_hidden + (size_t)u * 65536;
        float a = 0.f;
        #pragma unroll 16
        for (int h = 0; h < H_; ++h) a += sH[h] * Wh[(size_t)h * 256 + tid];
        sHt[tid] = a + b_hidden[(size_t)u * H_ + tid];
    }
    __syncthreads();
    // ---- stage 2: htpart[k] = ht_a @ W_lt1[u][0:H]
    {
        const float* Wl1a = W_lt1 + (size_t)u * 131072;
        float a = 0.f;
        #pragma unroll 16
        for (int h = 0; h < H_; ++h) a += sHt[h] * Wl1a[(size_t)h * 256 + tid];
        sHtp[tid] = a;
    }

    float acc[4][4][4];
    #pragma unroll
    for (int mt = 0; mt < 4; ++mt)
        #pragma unroll
        for (int nt = 0; nt < 4; ++nt)
            #pragma unroll
            for (int i = 0; i < 4; ++i) acc[mt][nt][i] = 0.f;

    // ---- GEMM1: io_a = X @ W_inter[u]
    w_store32(pf, smb, AT_WHI, AT_WLO, tid);
    __syncthreads();
    for (int c = 0; c < 8; ++c) {
        if (c < 7) w_ldg32(pf, Wi, (c + 1) * 32, tid);
        mma_chunk32(acc, sma + AT_XHI, sma + AT_XLO, (uint32_t)c * 64u,
                    sma + AT_WHI, sma + AT_WLO, lane, wid);
        __syncthreads();
        if (c < 7) { w_store32(pf, smb, AT_WHI, AT_WLO, tid); __syncthreads(); }
    }

    // prefetch GEMM2 chunk 0
    w_ldg32(pf, Wl1b, 0, tid);

    // ---- epilogue 1: io_a + b_inter -> bf16 hi/lo tiles (A of GEMM2)
    const int rq = lane >> 2, cq = (lane & 3) * 2;
    #pragma unroll
    for (int mt = 0; mt < 4; ++mt)
        #pragma unroll
        for (int nt = 0; nt < 4; ++nt) {
            int n0 = wid * 32 + nt * 8 + cq;
            float bi0 = sBi[n0], bi1 = sBi[n0 + 1];
            #pragma unroll
            for (int half = 0; half < 2; ++half) {
                float v0 = acc[mt][nt][half * 2 + 0] + bi0;
                float v1 = acc[mt][nt][half * 2 + 1] + bi1;
                __nv_bfloat16 h0 = __float2bfloat16(v0), h1 = __float2bfloat16(v1);
                __nv_bfloat16 l0 = __float2bfloat16(v0 - __bfloat162float(h0));
                __nv_bfloat16 l1 = __float2bfloat16(v1 - __bfloat162float(h1));
                int m = mt * 16 + rq + 8 * half;
                uint32_t off = (uint32_t)m * PITCH + (uint32_t)n0 * 2u;
                __nv_bfloat162 vh; vh.x = h0; vh.y = h1;
                __nv_bfloat162 vl; vl.x = l0; vl.y = l1;
                *(__nv_bfloat162*)(smb + AT_IOHI + off) = vh;
                *(__nv_bfloat162*)(smb + AT_IOLO + off) = vl;
                acc[mt][nt][half * 2 + 0] = 0.f;
                acc[mt][nt][half * 2 + 1] = 0.f;
            }
        }
    __syncthreads();

    // ---- GEMM2: pre-tanh = io_a @ W_lt1[u][H:2H]
    w_store32(pf, smb, AT_WHI, AT_WLO, tid);
    __syncthreads();
    for (int c = 0; c < 8; ++c) {
        if (c < 7) w_ldg32(pf, Wl1b, (c + 1) * 32, tid);
        mma_chunk32(acc, sma + AT_IOHI, sma + AT_IOLO, (uint32_t)c * 64u,
                    sma + AT_WHI, sma + AT_WLO, lane, wid);
        __syncthreads();
        if (c < 7) { w_store32(pf, smb, AT_WHI, AT_WLO, tid); __syncthreads(); }
    }

    // ---- epilogue 2: energies = sum_n tanh(acc + htpart + b_lt1) * W_scale
    {
        float ep[4][2];
        #pragma unroll
        for (int mt = 0; mt < 4; ++mt) { ep[mt][0] = 0.f; ep[mt][1] = 0.f; }
        #pragma unroll
        for (int mt = 0; mt < 4; ++mt)
            #pragma unroll
            for (int nt = 0; nt < 4; ++nt) {
                int n0 = wid * 32 + nt * 8 + cq;
                float add0 = sHtp[n0] + sBl[n0], add1 = sHtp[n0 + 1] + sBl[n0 + 1];
                float ws0 = sWs[n0], ws1 = sWs[n0 + 1];
                #pragma unroll
                for (int half = 0; half < 2; ++half) {
                    ep[mt][half] += tanhf(acc[mt][nt][half * 2 + 0] + add0) * ws0
                                  + tanhf(acc[mt][nt][half * 2 + 1] + add1) * ws1;
                }
            }
        #pragma unroll
        for (int mt = 0; mt < 4; ++mt)
            #pragma unroll
            for (int half = 0; half < 2; ++half) {
                float v = ep[mt][half];
                v += __shfl_xor_sync(0xffffffffu, v, 1);
                v += __shfl_xor_sync(0xffffffffu, v, 2);
                if ((lane & 3) == 0)
                    atomicAdd(&sE[mt * 16 + rq + 8 * half], v);
            }
    }
    __syncthreads();

    // ---- softmax over 64 (warp 0)
    if (tid < 32) {
        float e0 = sE[tid], e1 = sE[tid + 32];
        float mx = fmaxf(e0, e1);
        #pragma unroll
        for (int o = 16; o > 0; o >>= 1) mx = fmaxf(mx, __shfl_xor_sync(0xffffffffu, mx, o));
        float x0 = expf(e0 - mx), x1 = expf(e1 - mx);
        float s = x0 + x1;
        #pragma unroll
        for (int o = 16; o > 0; o >>= 1) s += __shfl_xor_sync(0xffffffffu, s, o);
        float inv = 1.f / s;
        x0 *= inv; x1 *= inv;
        sA[tid] = x0; sA[tid + 32] = x1;
        out_attn[(size_t)b * M_ + tid]      = x0;
        out_attn[(size_t)b * M_ + tid + 32] = x1;
    }
    __syncthreads();

    // ---- context[h] = sum_m attn[m] * X[m][h]  (X = hi + lo)
    {
        float c = 0.f;
        #pragma unroll 8
        for (int m = 0; m < M_; ++m) {
            uint32_t off = (uint32_t)m * PITCH + (uint32_t)tid * 2u;
            float xv = __bfloat162float(*(const __nv_bfloat16*)(smb + AT_XHI + off))
                     + __bfloat162float(*(const __nv_bfloat16*)(smb + AT_XLO + off));
            c += sA[m] * xv;
        }
        xcat[(size_t)b * 512 + 256 + tid] = c;
        xcat[(size_t)b * 512 + tid]       = emb[(size_t)b * E_ + tid];
    }
}

// ---------------------------------------------------------------------------
// Generic SIMT GEMM (gi/gh): C[m,n] = bias[n] + sum_k A[m,k]*B[n,k]
// ---------------------------------------------------------------------------
#define GEMM_SSTORE()                                                   \
    do {                                                                \
        int kq4 = (tid & 3) * 4;                                        \
        sAt[(kq4 + 0) * 64 + a_m] = pa.x;                               \
        sAt[(kq4 + 1) * 64 + a_m] = pa.y;                               \
        sAt[(kq4 + 2) * 64 + a_m] = pa.z;                               \
        sAt[(kq4 + 3) * 64 + a_m] = pa.w;                               \
        sBt[(kq4 + 0) * 128 + bn0] = pb0.x;                             \
        sBt[(kq4 + 1) * 128 + bn0] = pb0.y;                             \
        sBt[(kq4 + 2) * 128 + bn0] = pb0.z;                             \
        sBt[(kq4 + 3) * 128 + bn0] = pb0.w;                             \
        sBt[(kq4 + 0) * 128 + bn1] = pb1.x;                             \
        sBt[(kq4 + 1) * 128 + bn1] = pb1.y;                             \
        sBt[(kq4 + 2) * 128 + bn1] = pb1.z;                             \
        sBt[(kq4 + 3) * 128 + bn1] = pb1.w;                             \
    } while (0)

__global__ void __launch_bounds__(256) gemm_tn_bias(
    const float* __restrict__ A, const float* __restrict__ Bm,
    const float* __restrict__ bias, float* __restrict__ C,
    int Mrows, int N, int K)
{
    __shared__ float sAt[16 * 64];
    __shared__ float sBt[16 * 128];
    const int tid = threadIdx.x;
    const int mb = blockIdx.y * 64;
    const int nb = blockIdx.x * 128;

    const int a_m = tid >> 2;
    const int bn0 = tid >> 2;
    const int bn1 = 64 + (tid >> 2);
    const int nr0 = min(nb + bn0, N - 1);
    const int nr1 = min(nb + bn1, N - 1);

    const float* Arow  = A  + (size_t)(mb + a_m) * K + (tid & 3) * 4;
    const float* Brow0 = Bm + (size_t)nr0 * K + (tid & 3) * 4;
    const float* Brow1 = Bm + (size_t)nr1 * K + (tid & 3) * 4;

    float4 pa  = *(const float4*)(Arow);
    float4 pb0 = *(const float4*)(Brow0);
    float4 pb1 = *(const float4*)(Brow1);
    GEMM_SSTORE();
    __syncthreads();

    float acc[4][8];
    #pragma unroll
    for (int mi = 0; mi < 4; ++mi)
        #pragma unroll
        for (int ni = 0; ni < 8; ++ni) acc[mi][ni] = 0.f;

    const int tn  = tid & 15;
    const int tmg = tid >> 4;

    for (int k0 = 16;; k0 += 16) {
        const bool more = (k0 < K);
        if (more) {
            pa  = *(const float4*)(Arow + k0);
            pb0 = *(const float4*)(Brow0 + k0);
            pb1 = *(const float4*)(Brow1 + k0);
        }
        #pragma unroll
        for (int kk = 0; kk < 16; ++kk) {
            float4 av  = *(const float4*)&sAt[kk * 64 + tmg * 4];
            float4 bv0 = *(const float4*)&sBt[kk * 128 + tn * 4];
            float4 bv1 = *(const float4*)&sBt[kk * 128 + 64 + tn * 4];
            float aa[4] = {av.x, av.y, av.z, av.w};
            float bb[8] = {bv0.x, bv0.y, bv0.z, bv0.w, bv1.x, bv1.y, bv1.z, bv1.w};
            #pragma unroll
            for (int mi = 0; mi < 4; ++mi)
                #pragma unroll
                for (int ni = 0; ni < 8; ++ni) acc[mi][ni] += aa[mi] * bb[ni];
        }
        if (!more) break;
        __syncthreads();
        GEMM_SSTORE();
        __syncthreads();
    }

    #pragma unroll
    for (int half = 0; half < 2; ++half) {
        int n0 = nb + half * 64 + tn * 4;
        if (n0 < N) {
            float4 bv;
            bv.x = bias ? bias[n0 + 0] : 0.f;
            bv.y = bias ? bias[n0 + 1] : 0.f;
            bv.z = bias ? bias[n0 + 2] : 0.f;
            bv.w = bias ? bias[n0 + 3] : 0.f;
            #pragma unroll
            for (int mi = 0; mi < 4; ++mi) {
                int m = mb + tmg * 4 + mi;
                float4 v;
                v.x = acc[mi][half * 4 + 0] + bv.x;
                v.y = acc[mi][half * 4 + 1] + bv.y;
                v.z = acc[mi][half * 4 + 2] + bv.z;
                v.w = acc[mi][half * 4 + 3] + bv.w;
                *(float4*)&C[(size_t)m * N + n0] = v;
            }
        }
    }
}

// ---------------------------------------------------------------------------
// GRU gate fusion
// ---------------------------------------------------------------------------
__global__ void gru_gate_kernel(
    const float* __restrict__ gi, const float* __restrict__ gh,
    const float* __restrict__ hidden,
    float* __restrict__ hid_out, float* __restrict__ gru_out)
{
    int idx = blockIdx.x * 256 + threadIdx.x;
    int b = idx >> 8, h = idx & 255;
    const float* gib = gi + (size_t)b * 768;
    const float* ghb = gh + (size_t)b * 768;
    float ir = gib[h], iz = gib[256 + h], in_ = gib[512 + h];
    float hr = ghb[h], hz = ghb[256 + h], hn = ghb[512 + h];
    float r = 1.f / (1.f + expf(-(ir + hr)));
    float z = 1.f / (1.f + expf(-(iz + hz)));
    float nc = tanhf(in_ + r * hn);
    float h0 = hidden[idx];
    float hv = (1.f - z) * nc + z * h0;
    hid_out[idx] = hv;
    gru_out[idx] = hv;
}

// ---------------------------------------------------------------------------
// Split-bf16 conversion kernels (vocab operands)
// ---------------------------------------------------------------------------
__global__ void cvt_b_kernel(const float* __restrict__ W,
                             __nv_bfloat16* __restrict__ hi,
                             __nv_bfloat16* __restrict__ lo)
{
    size_t r = blockIdx.x;
    int c = threadIdx.x;
    size_t i = r * H_ + c;
    float v = (r < V_) ? W[i] : 0.f;
    __nv_bfloat16 h = __float2bfloat16(v);
    float res = v - __bfloat162float(h);
    hi[i] = h;
    lo[i] = __float2bfloat16(res);
}

__global__ void cvt_a_kernel(const float* __restrict__ A,
                             __nv_bfloat16* __restrict__ hi,
                             __nv_bfloat16* __restrict__ lo)
{
    size_t i = (size_t)blockIdx.x * 256 + threadIdx.x;
    float v = A[i];
    __nv_bfloat16 h = __float2bfloat16(v);
    float res = v - __bfloat162float(h);
    hi[i] = h;
    lo[i] = __float2bfloat16(res);
}

// ---------------------------------------------------------------------------
// mma.sync vocab GEMM (unchanged from R6, passing at rel_err 4.5e-6)
// ---------------------------------------------------------------------------
#define VROW 144u
#define VTILE_BYTES (128u * VROW)
#define VSTAGE_BYTES (4u * VTILE_BYTES)
#define VSMEM_BYTES  (2u * VSTAGE_BYTES)

#define VOFF_AHI 0u
#define VOFF_ALO VTILE_BYTES
#define VOFF_BHI (2u * VTILE_BYTES)
#define VOFF_BLO (3u * VTILE_BYTES)

__device__ __forceinline__ void v_load_chunk(
    uint32_t sbase,
    const __nv_bfloat16* __restrict__ Ahi, const __nv_bfloat16* __restrict__ Alo,
    const __nv_bfloat16* __restrict__ Bhi, const __nv_bfloat16* __restrict__ Blo,
    size_t mb, size_t nb, int kc, int tid)
{
    const size_t koff = (size_t)kc * 64;
    #pragma unroll
    for (int it = 0; it < 4; ++it) {
        int idx = tid + it * 256;
        int r = idx >> 3, c = idx & 7;
        uint32_t soff = (uint32_t)r * VROW + (uint32_t)c * 16u;
        const __nv_bfloat16* ga = Ahi + (mb + r) * H_ + koff + c * 8;
        CP_ASYNC16(sbase + VOFF_AHI + soff, ga);
        const __nv_bfloat16* ga2 = Alo + (mb + r) * H_ + koff + c * 8;
        CP_ASYNC16(sbase + VOFF_ALO + soff, ga2);
        const __nv_bfloat16* gb = Bhi + (nb + r) * H_ + koff + c * 8;
        CP_ASYNC16(sbase + VOFF_BHI + soff, gb);
        const __nv_bfloat16* gb2 = Blo + (nb + r) * H_ + koff + c * 8;
        CP_ASYNC16(sbase + VOFF_BLO + soff, gb2);
    }
}

__global__ void __launch_bounds__(256, 1) vocab_mma_kernel(
    const __nv_bfloat16* __restrict__ Ahi, const __nv_bfloat16* __restrict__ Alo,
    const __nv_bfloat16* __restrict__ Bhi, const __nv_bfloat16* __restrict__ Blo,
    const float* __restrict__ bias, float* __restrict__ C)
{
    extern __shared__ char smraw[];
    const uint32_t smb = smem_u32(smraw);

    const int tid  = threadIdx.x;
    const int wid  = tid >> 5;
    const int lane = tid & 31;
    const int wm   = wid & 1;
    const int wn   = wid >> 1;
    const size_t mb = (size_t)blockIdx.x * 128;
    const size_t nb = (size_t)blockIdx.y * 128;

    const int lr = lane & 7;
    const int lg = lane >> 3;

    uint32_t aRow[4], bRow[2];
    #pragma unroll
    for (int mt = 0; mt < 4; ++mt)
        aRow[mt] = (uint32_t)(wm * 64 + mt * 16 + lr + (lg & 1) * 8) * VROW
                 + (uint32_t)((lg >> 1) * 16);
    #pragma unroll
    for (int p = 0; p < 2; ++p)
        bRow[p] = (uint32_t)(wn * 32 + p * 16 + lr + (lg >> 1) * 8) * VROW
                + (uint32_t)((lg & 1) * 16);

    float acc[4][4][4];
    #pragma unroll
    for (int mt = 0; mt < 4; ++mt)
        #pragma unroll
        for (int nt = 0; nt < 4; ++nt)
            #pragma unroll
            for (int i = 0; i < 4; ++i) acc[mt][nt][i] = 0.f;

    v_load_chunk(smb, Ahi, Alo, Bhi, Blo, mb, nb, 0, tid);
    CP_COMMIT();

    for (int ch = 0; ch < 4; ++ch) {
        const uint32_t st = (uint32_t)(ch & 1) * VSTAGE_BYTES;
        if (ch < 3) {
            v_load_chunk(smb + ((uint32_t)((ch + 1) & 1) * VSTAGE_BYTES),
                         Ahi, Alo, Bhi, Blo, mb, nb, ch + 1, tid);
            CP_COMMIT();
            CP_WAIT1();
        } else {
            CP_WAIT0();
        }
        __syncthreads();

        const uint32_t aHiB = smb + st + VOFF_AHI;
        const uint32_t aLoB = smb + st + VOFF_ALO;
        const uint32_t bHiB = smb + st + VOFF_BHI;
        const uint32_t bLoB = smb + st + VOFF_BLO;

        #pragma unroll
        for (int ks = 0; ks < 4; ++ks) {
            const uint32_t kso = (uint32_t)ks * 32u;
            uint32_t ah[4][4], al[4][4];
            #pragma unroll
            for (int mt = 0; mt < 4; ++mt) {
                LDSM4(ah[mt][0], ah[mt][1], ah[mt][2], ah[mt][3], aHiB + aRow[mt] + kso);
                LDSM4(al[mt][0], al[mt][1], al[mt][2], al[mt][3], aLoB + aRow[mt] + kso);
            }
            uint32_t bh[4][2], bl[4][2];
            #pragma unroll
            for (int p = 0; p < 2; ++p) {
                LDSM4(bh[2 * p][0], bh[2 * p][1], bh[2 * p + 1][0], bh[2 * p + 1][1],
                      bHiB + bRow[p] + kso);
                LDSM4(bl[2 * p][0], bl[2 * p][1], bl[2 * p + 1][0], bl[2 * p + 1][1],
                      bLoB + bRow[p] + kso);
            }
            #pragma unroll
            for (int mt = 0; mt < 4; ++mt)
                #pragma unroll
                for (int nt = 0; nt < 4; ++nt) {
                    MMA_BF16(acc[mt][nt], ah[mt], bh[nt]);
                    MMA_BF16(acc[mt][nt], ah[mt], bl[nt]);
                    MMA_BF16(acc[mt][nt], al[mt], bh[nt]);
                }
        }
        __syncthreads();
    }

    const int rq = lane >> 2, cq = (lane & 3) * 2;
    #pragma unroll
    for (int nt = 0; nt < 4; ++nt) {
        const size_t col = nb + (size_t)wn * 32 + nt * 8 + cq;
        if (col < (size_t)V_) {
            const float2 bv = *(const float2*)&bias[col];
            #pragma unroll
            for (int mt = 0; mt < 4; ++mt) {
                const size_t row0 = mb + (size_t)wm * 64 + mt * 16 + rq;
                float2 v0, v1;
                v0.x = acc[mt][nt][0] + bv.x;
                v0.y = acc[mt][nt][1] + bv.y;
                v1.x = acc[mt][nt][2] + bv.x;
                v1.y = acc[mt][nt][3] + bv.y;
                *(float2*)&C[row0 * V_ + col]       = v0;
                *(float2*)&C[(row0 + 8) * V_ + col] = v1;
            }
        }
    }
}

// ---------------------------------------------------------------------------
extern "C" void kernel_launch(void* const* d_in, const int* in_sizes, int n_in,
                              void* d_out, int out_size)
{
    (void)in_sizes; (void)n_in; (void)out_size;
    const float* emb      = (const float*)d_in[0];
    const float* hidden   = (const float*)d_in[1];
    const float* inter    = (const float*)d_in[2];
    const float* W_inter  = (const float*)d_in[4];
    const float* b_inter  = (const float*)d_in[5];
    const float* W_hidden = (const float*)d_in[6];
    const float* b_hidden = (const float*)d_in[7];
    const float* W_scale  = (const float*)d_in[8];
    const float* b_scale  = (const float*)d_in[9];
    const float* W_lt1    = (const float*)d_in[10];
    const float* b_lt1    = (const float*)d_in[11];
    const float* W_ih     = (const float*)d_in[12];
    const float* W_hh     = (const float*)d_in[13];
    const float* b_ih     = (const float*)d_in[14];
    const float* b_hh     = (const float*)d_in[15];
    const float* W_out    = (const float*)d_in[16];
    const float* b_out    = (const float*)d_in[17];
    const int* user_list  = (const int*)d_in[19];
    float* out = (float*)d_out;

    cudaFuncSetAttribute(attn_mma_kernel,
                         cudaFuncAttributeMaxDynamicSharedMemorySize,
                         AT_BYTES);
    cudaFuncSetAttribute(vocab_mma_kernel,
                         cudaFuncAttributeMaxDynamicSharedMemorySize,
                         VSMEM_BYTES);

    void *p_xcat = nullptr, *p_gi = nullptr, *p_gh = nullptr, *p_perm = nullptr;
    void *p_bhi = nullptr, *p_blo = nullptr, *p_ahi = nullptr, *p_alo = nullptr;
    cudaGetSymbolAddress(&p_xcat, g_xcat);
    cudaGetSymbolAddress(&p_gi, g_gi);
    cudaGetSymbolAddress(&p_gh, g_gh);
    cudaGetSymbolAddress(&p_perm, g_perm);
    cudaGetSymbolAddress(&p_bhi, g_b_hi);
    cudaGetSymbolAddress(&p_blo, g_b_lo);
    cudaGetSymbolAddress(&p_ahi, g_a_hi);
    cudaGetSymbolAddress(&p_alo, g_a_lo);

    // 0) user sort (L2 locality for gathered weights) + vocab weight convert
    sort_users_kernel<<<1, 1024>>>(user_list, (int*)p_perm);
    cvt_b_kernel<<<VPAD_, 256>>>(W_out, (__nv_bfloat16*)p_bhi, (__nv_bfloat16*)p_blo);

    // 1) tensor-core attention -> attn out + xcat scratch
    attn_mma_kernel<<<B_, 256, AT_BYTES>>>(
        inter, hidden, emb,
        W_inter, b_inter, W_hidden, b_hidden,
        W_scale, b_scale, W_lt1, b_lt1,
        user_list, (const int*)p_perm, out + ATTN_OFF, (float*)p_xcat);

    // 2) gi = xcat @ W_ih^T + b_ih
    {
        dim3 grid(768 / 128, B_ / 64);
        gemm_tn_bias<<<grid, 256>>>((const float*)p_xcat, W_ih, b_ih,
                                    (float*)p_gi, B_, 768, 512);
    }
    // 3) gh = h0 @ W_hh^T + b_hh
    {
        dim3 grid(768 / 128, B_ / 64);
        gemm_tn_bias<<<grid, 256>>>(hidden, W_hh, b_hh,
                                    (float*)p_gh, B_, 768, 256);
    }
    // 4) gates -> h_new
    gru_gate_kernel<<<(B_ * H_) / 256, 256>>>(
        (const float*)p_gi, (const float*)p_gh, hidden,
        out + HID_OFF, out + GRU_OFF);

    // 5) h_new -> split bf16
    cvt_a_kernel<<<(B_ * H_) / 256, 256>>>(out + HID_OFF,
                                           (__nv_bfloat16*)p_ahi,
                                           (__nv_bfloat16*)p_alo);

    // 6) output = h_new @ W_out^T + b_out  (mma.sync split-bf16)
    {
        dim3 grid(B_ / 128, VPAD_ / 128);
        vocab_mma_kernel<<<grid, 256, VSMEM_BYTES>>>(
            (const __nv_bfloat16*)p_ahi, (const __nv_bfloat16*)p_alo,
            (const __nv_bfloat16*)p_bhi, (const __nv_bfloat16*)p_blo,
            b_out, out + OUT_OFF);
    }

    // 7) emb passthrough output
    cudaMemcpyAsync(out + EMB_OFF, emb, (size_t)B_ * E_ * sizeof(float),
                    cudaMemcpyDeviceToDevice, 0);
}

// round 11
// speedup vs baseline: 3.2087x; 1.2687x over previous
#include <cuda_runtime.h>
#include <cuda_bf16.h>
#include <math.h>
#include <stdint.h>

#define B_ 2048
#define M_ 64
#define H_ 256
#define E_ 256
#define U_ 1000
#define V_ 50000
#define VPAD_ 50176   // 392 * 128

// Output buffer layout (f32, concatenated in reference-return order)
static const size_t OUT_OFF  = 0;                               // (B,1,V)
static const size_t HID_OFF  = (size_t)B_ * V_;                 // (1,B,H)
static const size_t EMB_OFF  = HID_OFF + (size_t)B_ * H_;       // (B,1,E)
static const size_t GRU_OFF  = EMB_OFF + (size_t)B_ * E_;       // (B,1,H)
static const size_t ATTN_OFF = GRU_OFF + (size_t)B_ * H_;       // (B,M)

// Scratch (static device arrays; no allocation allowed)
__device__ __align__(16) float g_gi[(size_t)B_ * 768];
__device__ __align__(16) float g_gh[(size_t)B_ * 768];
__device__ __align__(16) float g_htp[(size_t)B_ * H_];
__device__ int g_perm[B_];
// split-bf16 operands
__device__ __align__(16) __nv_bfloat16 g_b_hi[(size_t)VPAD_ * H_];
__device__ __align__(16) __nv_bfloat16 g_b_lo[(size_t)VPAD_ * H_];
__device__ __align__(16) __nv_bfloat16 g_a_hi[(size_t)B_ * H_];
__device__ __align__(16) __nv_bfloat16 g_a_lo[(size_t)B_ * H_];
__device__ __align__(16) __nv_bfloat16 g_xc_hi[(size_t)B_ * 512];
__device__ __align__(16) __nv_bfloat16 g_xc_lo[(size_t)B_ * 512];
__device__ __align__(16) __nv_bfloat16 g_wih_hi[(size_t)768 * 512];
__device__ __align__(16) __nv_bfloat16 g_wih_lo[(size_t)768 * 512];
__device__ __align__(16) __nv_bfloat16 g_whh_hi[(size_t)768 * 256];
__device__ __align__(16) __nv_bfloat16 g_whh_lo[(size_t)768 * 256];
__device__ __align__(16) __nv_bfloat16 g_hid_hi[(size_t)B_ * 256];
__device__ __align__(16) __nv_bfloat16 g_hid_lo[(size_t)B_ * 256];

// ===========================================================================
// PTX helpers (family-portable: mma.sync / ldmatrix / cp.async only)
// ===========================================================================
__device__ __forceinline__ uint32_t smem_u32(const void* p) {
    uint32_t a;
    asm("{ .reg .u64 t; cvta.to.shared.u64 t, %1; cvt.u32.u64 %0, t; }" : "=r"(a) : "l"(p));
    return a;
}
#define LDSM4(r0, r1, r2, r3, addr) \
    asm volatile("ldmatrix.sync.aligned.m8n8.x4.shared.b16 {%0,%1,%2,%3}, [%4];" \
        : "=r"(r0), "=r"(r1), "=r"(r2), "=r"(r3) : "r"(addr))
#define LDSM4T(r0, r1, r2, r3, addr) \
    asm volatile("ldmatrix.sync.aligned.m8n8.x4.trans.shared.b16 {%0,%1,%2,%3}, [%4];" \
        : "=r"(r0), "=r"(r1), "=r"(r2), "=r"(r3) : "r"(addr))
#define MMA_BF16(d, a, b) \
    asm volatile("mma.sync.aligned.m16n8k16.row.col.f32.bf16.bf16.f32 " \
        "{%0,%1,%2,%3}, {%4,%5,%6,%7}, {%8,%9}, {%0,%1,%2,%3};" \
        : "+f"((d)[0]), "+f"((d)[1]), "+f"((d)[2]), "+f"((d)[3]) \
        : "r"((a)[0]), "r"((a)[1]), "r"((a)[2]), "r"((a)[3]), "r"((b)[0]), "r"((b)[1]))
#define CP_ASYNC16(dst, src) \
    asm volatile("cp.async.cg.shared.global [%0], [%1], 16;" :: "r"(dst), "l"(src))
#define CP_COMMIT() asm volatile("cp.async.commit_group;" ::: "memory")
#define CP_WAIT1()  asm volatile("cp.async.wait_group 1;" ::: "memory")
#define CP_WAIT0()  asm volatile("cp.async.wait_group 0;" ::: "memory")

// ---------------------------------------------------------------------------
// User counting sort (L2 locality for gathered weights).
// ---------------------------------------------------------------------------
__global__ void __launch_bounds__(1024) sort_users_kernel(
    const int* __restrict__ ul, int* __restrict__ perm)
{
    __shared__ int hist[1024];
    __shared__ int wsums[32];
    const int tid = threadIdx.x;
    hist[tid] = 0;
    __syncthreads();
    atomicAdd(&hist[ul[tid]], 1);
    atomicAdd(&hist[ul[tid + 1024]], 1);
    __syncthreads();
    int c = hist[tid];
    int v = c;
    #pragma unroll
    for (int o = 1; o < 32; o <<= 1) {
        int t = __shfl_up_sync(0xffffffffu, v, o);
        if ((tid & 31) >= o) v += t;
    }
    if ((tid & 31) == 31) wsums[tid >> 5] = v;
    __syncthreads();
    if (tid < 32) {
        int w = wsums[tid];
        #pragma unroll
        for (int o = 1; o < 32; o <<= 1) {
            int t = __shfl_up_sync(0xffffffffu, w, o);
            if (tid >= o) w += t;
        }
        wsums[tid] = w;
    }
    __syncthreads();
    int excl = v - c + ((tid >= 32) ? wsums[(tid >> 5) - 1] : 0);
    __syncthreads();
    hist[tid] = excl;
    __syncthreads();
    { int b = tid;        perm[atomicAdd(&hist[ul[b]], 1)] = b; }
    { int b = tid + 1024; perm[atomicAdd(&hist[ul[b]], 1)] = b; }
}

// ---------------------------------------------------------------------------
// htpart pre-kernel:  htpart = (h0 @ W_hidden[u] + b_hidden[u]) @ W_lt1[u][0:H]
// ---------------------------------------------------------------------------
__global__ void __launch_bounds__(256) htpart_kernel(
    const float* __restrict__ hidden,
    const float* __restrict__ W_hidden, const float* __restrict__ b_hidden,
    const float* __restrict__ W_lt1,
    const int* __restrict__ ul, const int* __restrict__ perm,
    float* __restrict__ htp)
{
    __shared__ float sH[256];
    __shared__ float sHt[256];
    const int tid = threadIdx.x;
    const int b = perm[blockIdx.x];
    const int u = ul[b];
    sH[tid] = hidden[(size_t)b * H_ + tid];
    __syncthreads();
    {
        const float* Wh = W_hidden + (size_t)u * 65536;
        float a = 0.f;
        #pragma unroll 16
        for (int h = 0; h < H_; ++h) a += sH[h] * Wh[(size_t)h * 256 + tid];
        sHt[tid] = a + b_hidden[(size_t)u * H_ + tid];
    }
    __syncthreads();
    {
        const float* Wl = W_lt1 + (size_t)u * 131072;
        float a = 0.f;
        #pragma unroll 16
        for (int h = 0; h < H_; ++h) a += sHt[h] * Wl[(size_t)h * 256 + tid];
        htp[(size_t)b * H_ + tid] = a;
    }
}

// ===========================================================================
// Tensor-core attention kernel.  One CTA (256 thr, 8 warps) per batch.
// ===========================================================================
#define PITCH 528u
#define AT_XHI  0u
#define AT_XLO  33792u
#define AT_IOHI 67584u
#define AT_IOLO 101376u
#define AT_WHI  135168u          // 32 rows x 528
#define AT_WLO  152064u
#define AT_FLT  168960u          // float region
#define AT_BYTES 175616u

__device__ __forceinline__ void w_ldg32(float2 (&pf)[16],
                                        const float* __restrict__ src,
                                        int h0, int tid)
{
    #pragma unroll
    for (int i = 0; i < 16; ++i) {
        int p = tid + i * 256;
        int hl = p >> 7, n2 = p & 127;
        pf[i] = *(const float2*)(src + (size_t)(h0 + hl) * 256 + n2 * 2);
    }
}

__device__ __forceinline__ void w_store32(const float2 (&pf)[16], char* smb,
                                          uint32_t offHi, uint32_t offLo, int tid)
{
    #pragma unroll
    for (int i = 0; i < 16; ++i) {
        int p = tid + i * 256;
        int hl = p >> 7, n2 = p & 127;
        float x = pf[i].x, y = pf[i].y;
        __nv_bfloat16 hx = __float2bfloat16(x), hy = __float2bfloat16(y);
        __nv_bfloat16 lx = __float2bfloat16(x - __bfloat162float(hx));
        __nv_bfloat16 ly = __float2bfloat16(y - __bfloat162float(hy));
        uint32_t off = (uint32_t)hl * PITCH + (uint32_t)n2 * 4u;
        __nv_bfloat162 vh; vh.x = hx; vh.y = hy;
        __nv_bfloat162 vl; vl.x = lx; vl.y = ly;
        *(__nv_bfloat162*)(smb + offHi + off) = vh;
        *(__nv_bfloat162*)(smb + offLo + off) = vl;
    }
}

__device__ __forceinline__ void mma_chunk32(
    float (&acc)[4][4][4],
    uint32_t aHi, uint32_t aLo, uint32_t aKByte,
    uint32_t wHi, uint32_t wLo, int lane, int wid)
{
    const int lr = lane & 7, lg = lane >> 3;
    const int bkr = (lane & 7) + 8 * ((lane >> 3) & 1);
    const uint32_t bnb = (uint32_t)(wid * 64 + 16 * (lane >> 4));
    #pragma unroll
    for (int ks = 0; ks < 2; ++ks) {
        const uint32_t akb = aKByte + (uint32_t)ks * 32u;
        uint32_t ah[4][4], al[4][4];
        #pragma unroll
        for (int mt = 0; mt < 4; ++mt) {
            uint32_t ar = (uint32_t)(mt * 16 + lr + (lg & 1) * 8) * PITCH
                        + (uint32_t)((lg >> 1) * 16) + akb;
            LDSM4(ah[mt][0], ah[mt][1], ah[mt][2], ah[mt][3], aHi + ar);
            LDSM4(al[mt][0], al[mt][1], al[mt][2], al[mt][3], aLo + ar);
        }
        uint32_t bh[2][4], bl[2][4];
        #pragma unroll
        for (int p = 0; p < 2; ++p) {
            uint32_t br = (uint32_t)(ks * 16 + bkr) * PITCH + bnb + (uint32_t)p * 32u;
            LDSM4T(bh[p][0], bh[p][1], bh[p][2], bh[p][3], wHi + br);
            LDSM4T(bl[p][0], bl[p][1], bl[p][2], bl[p][3], wLo + br);
        }
        #pragma unroll
        for (int mt = 0; mt < 4; ++mt)
            #pragma unroll
            for (int nt = 0; nt < 4; ++nt) {
                const uint32_t* bhp = &bh[nt >> 1][(nt & 1) * 2];
                const uint32_t* blp = &bl[nt >> 1][(nt & 1) * 2];
                MMA_BF16(acc[mt][nt], ah[mt], bhp);
                MMA_BF16(acc[mt][nt], ah[mt], blp);
                MMA_BF16(acc[mt][nt], al[mt], bhp);
            }
    }
}

__global__ void __launch_bounds__(256, 1) attn_mma_kernel(
    const float* __restrict__ X_all,
    const float* __restrict__ emb,
    const float* __restrict__ W_inter, const float* __restrict__ b_inter,
    const float* __restrict__ W_scale, const float* __restrict__ b_scale,
    const float* __restrict__ W_lt1, const float* __restrict__ b_lt1,
    const int* __restrict__ user_list,
    const int* __restrict__ perm,
    const float* __restrict__ htp,
    float* __restrict__ out_attn,
    __nv_bfloat16* __restrict__ xc_hi,
    __nv_bfloat16* __restrict__ xc_lo)
{
    extern __shared__ char smraw[];
    char* smb = smraw;
    const uint32_t sma = smem_u32(smraw);
    float* sFlt = (float*)(smb + AT_FLT);
    float* sHtp = sFlt + 0;
    float* sBi  = sFlt + 256;
    float* sBl  = sFlt + 512;
    float* sWs  = sFlt + 768;
    float* sE   = sFlt + 1024;
    float* sA   = sFlt + 1088;

    const int tid  = threadIdx.x;
    const int lane = tid & 31;
    const int wid  = tid >> 5;
    const int b    = perm[blockIdx.x];
    const int u    = user_list[b];

    const float* Wi   = W_inter + (size_t)u * 65536;
    const float* Wl1b = W_lt1 + (size_t)u * 131072 + 65536;

    // ---- stage 0: X -> bf16 hi/lo tiles; vectors
    {
        const float* Xg = X_all + (size_t)b * (M_ * H_);
        #pragma unroll
        for (int i = 0; i < 32; ++i) {
            int p = tid + i * 256;
            int m = p >> 7, n2 = p & 127;
            float2 v = *(const float2*)(Xg + m * 256 + n2 * 2);
            __nv_bfloat16 hx = __float2bfloat16(v.x), hy = __float2bfloat16(v.y);
            __nv_bfloat16 lx = __float2bfloat16(v.x - __bfloat162float(hx));
            __nv_bfloat16 ly = __float2bfloat16(v.y - __bfloat162float(hy));
            uint32_t off = (uint32_t)m * PITCH + (uint32_t)n2 * 4u;
            __nv_bfloat162 vh; vh.x = hx; vh.y = hy;
            __nv_bfloat162 vl; vl.x = lx; vl.y = ly;
            *(__nv_bfloat162*)(smb + AT_XHI + off) = vh;
            *(__nv_bfloat162*)(smb + AT_XLO + off) = vl;
        }
    }
    sHtp[tid] = htp[(size_t)b * H_ + tid];
    sBi[tid]  = b_inter[(size_t)u * H_ + tid];
    sBl[tid]  = b_lt1[(size_t)u * H_ + tid];
    sWs[tid]  = W_scale[(size_t)u * H_ + tid];
    if (tid < 64) sE[tid] = b_scale[u];

    float2 pf[16];
    w_ldg32(pf, Wi, 0, tid);   // prefetch GEMM1 chunk 0

    float acc[4][4][4];
    #pragma unroll
    for (int mt = 0; mt < 4; ++mt)
        #pragma unroll
        for (int nt = 0; nt < 4; ++nt)
            #pragma unroll
            for (int i = 0; i < 4; ++i) acc[mt][nt][i] = 0.f;
    __syncthreads();

    // ---- GEMM1: io_a = X @ W_inter[u]
    w_store32(pf, smb, AT_WHI, AT_WLO, tid);
    __syncthreads();
    for (int c = 0; c < 8; ++c) {
        if (c < 7) w_ldg32(pf, Wi, (c + 1) * 32, tid);
        mma_chunk32(acc, sma + AT_XHI, sma + AT_XLO, (uint32_t)c * 64u,
                    sma + AT_WHI, sma + AT_WLO, lane, wid);
        __syncthreads();
        if (c < 7) { w_store32(pf, smb, AT_WHI, AT_WLO, tid); __syncthreads(); }
    }

    // prefetch GEMM2 chunk 0
    w_ldg32(pf, Wl1b, 0, tid);

    // ---- epilogue 1: io_a + b_inter -> bf16 hi/lo tiles (A of GEMM2)
    const int rq = lane >> 2, cq = (lane & 3) * 2;
    #pragma unroll
    for (int mt = 0; mt < 4; ++mt)
        #pragma unroll
        for (int nt = 0; nt < 4; ++nt) {
            int n0 = wid * 32 + nt * 8 + cq;
            float bi0 = sBi[n0], bi1 = sBi[n0 + 1];
            #pragma unroll
            for (int half = 0; half < 2; ++half) {
                float v0 = acc[mt][nt][half * 2 + 0] + bi0;
                float v1 = acc[mt][nt][half * 2 + 1] + bi1;
                __nv_bfloat16 h0 = __float2bfloat16(v0), h1 = __float2bfloat16(v1);
                __nv_bfloat16 l0 = __float2bfloat16(v0 - __bfloat162float(h0));
                __nv_bfloat16 l1 = __float2bfloat16(v1 - __bfloat162float(h1));
                int m = mt * 16 + rq + 8 * half;
                uint32_t off = (uint32_t)m * PITCH + (uint32_t)n0 * 2u;
                __nv_bfloat162 vh; vh.x = h0; vh.y = h1;
                __nv_bfloat162 vl; vl.x = l0; vl.y = l1;
                *(__nv_bfloat162*)(smb + AT_IOHI + off) = vh;
                *(__nv_bfloat162*)(smb + AT_IOLO + off) = vl;
                acc[mt][nt][half * 2 + 0] = 0.f;
                acc[mt][nt][half * 2 + 1] = 0.f;
            }
        }
    __syncthreads();

    // ---- GEMM2: pre-tanh = io_a @ W_lt1[u][H:2H]
    w_store32(pf, smb, AT_WHI, AT_WLO, tid);
    __syncthreads();
    for (int c = 0; c < 8; ++c) {
        if (c < 7) w_ldg32(pf, Wl1b, (c + 1) * 32, tid);
        mma_chunk32(acc, sma + AT_IOHI, sma + AT_IOLO, (uint32_t)c * 64u,
                    sma + AT_WHI, sma + AT_WLO, lane, wid);
        __syncthreads();
        if (c < 7) { w_store32(pf, smb, AT_WHI, AT_WLO, tid); __syncthreads(); }
    }

    // ---- epilogue 2: energies = sum_n tanh(acc + htpart + b_lt1) * W_scale
    {
        float ep[4][2];
        #pragma unroll
        for (int mt = 0; mt < 4; ++mt) { ep[mt][0] = 0.f; ep[mt][1] = 0.f; }
        #pragma unroll
        for (int mt = 0; mt < 4; ++mt)
            #pragma unroll
            for (int nt = 0; nt < 4; ++nt) {
                int n0 = wid * 32 + nt * 8 + cq;
                float add0 = sHtp[n0] + sBl[n0], add1 = sHtp[n0 + 1] + sBl[n0 + 1];
                float ws0 = sWs[n0], ws1 = sWs[n0 + 1];
                #pragma unroll
                for (int half = 0; half < 2; ++half) {
                    ep[mt][half] += tanhf(acc[mt][nt][half * 2 + 0] + add0) * ws0
                                  + tanhf(acc[mt][nt][half * 2 + 1] + add1) * ws1;
                }
            }
        #pragma unroll
        for (int mt = 0; mt < 4; ++mt)
            #pragma unroll
            for (int half = 0; half < 2; ++half) {
                float v = ep[mt][half];
                v += __shfl_xor_sync(0xffffffffu, v, 1);
                v += __shfl_xor_sync(0xffffffffu, v, 2);
                if ((lane & 3) == 0)
                    atomicAdd(&sE[mt * 16 + rq + 8 * half], v);
            }
    }
    __syncthreads();

    // ---- softmax over 64 (warp 0)
    if (tid < 32) {
        float e0 = sE[tid], e1 = sE[tid + 32];
        float mx = fmaxf(e0, e1);
        #pragma unroll
        for (int o = 16; o > 0; o >>= 1) mx = fmaxf(mx, __shfl_xor_sync(0xffffffffu, mx, o));
        float x0 = expf(e0 - mx), x1 = expf(e1 - mx);
        float s = x0 + x1;
        #pragma unroll
        for (int o = 16; o > 0; o >>= 1) s += __shfl_xor_sync(0xffffffffu, s, o);
        float inv = 1.f / s;
        x0 *= inv; x1 *= inv;
        sA[tid] = x0; sA[tid + 32] = x1;
        out_attn[(size_t)b * M_ + tid]      = x0;
        out_attn[(size_t)b * M_ + tid + 32] = x1;
    }
    __syncthreads();

    // ---- context[h] = sum_m attn[m] * X[m][h]; xcat -> bf16 hi/lo
    {
        float c = 0.f;
        #pragma unroll 8
        for (int m = 0; m < M_; ++m) {
            uint32_t off = (uint32_t)m * PITCH + (uint32_t)tid * 2u;
            float xv = __bfloat162float(*(const __nv_bfloat16*)(smb + AT_XHI + off))
                     + __bfloat162float(*(const __nv_bfloat16*)(smb + AT_XLO + off));
            c += sA[m] * xv;
        }
        __nv_bfloat16 ch = __float2bfloat16(c);
        xc_hi[(size_t)b * 512 + 256 + tid] = ch;
        xc_lo[(size_t)b * 512 + 256 + tid] = __float2bfloat16(c - __bfloat162float(ch));
        float e = emb[(size_t)b * E_ + tid];
        __nv_bfloat16 eh = __float2bfloat16(e);
        xc_hi[(size_t)b * 512 + tid] = eh;
        xc_lo[(size_t)b * 512 + tid] = __float2bfloat16(e - __bfloat162float(eh));
    }
}

// ---------------------------------------------------------------------------
// GRU gate fusion
// ---------------------------------------------------------------------------
__global__ void gru_gate_kernel(
    const float* __restrict__ gi, const float* __restrict__ gh,
    const float* __restrict__ hidden,
    float* __restrict__ hid_out, float* __restrict__ gru_out)
{
    int idx = blockIdx.x * 256 + threadIdx.x;
    int b = idx >> 8, h = idx & 255;
    const float* gib = gi + (size_t)b * 768;
    const float* ghb = gh + (size_t)b * 768;
    float ir = gib[h], iz = gib[256 + h], in_ = gib[512 + h];
    float hr = ghb[h], hz = ghb[256 + h], hn = ghb[512 + h];
    float r = 1.f / (1.f + expf(-(ir + hr)));
    float z = 1.f / (1.f + expf(-(iz + hz)));
    float nc = tanhf(in_ + r * hn);
    float h0 = hidden[idx];
    float hv = (1.f - z) * nc + z * h0;
    hid_out[idx] = hv;
    gru_out[idx] = hv;
}

// ---------------------------------------------------------------------------
// Split-bf16 conversion kernels
// ---------------------------------------------------------------------------
__global__ void cvt_b_kernel(const float* __restrict__ W,
                             __nv_bfloat16* __restrict__ hi,
                             __nv_bfloat16* __restrict__ lo)
{
    size_t r = blockIdx.x;
    int c = threadIdx.x;
    size_t i = r * H_ + c;
    float v = (r < V_) ? W[i] : 0.f;
    __nv_bfloat16 h = __float2bfloat16(v);
    float res = v - __bfloat162float(h);
    hi[i] = h;
    lo[i] = __float2bfloat16(res);
}

__global__ void cvt_a_kernel(const float* __restrict__ A,
                             __nv_bfloat16* __restrict__ hi,
                             __nv_bfloat16* __restrict__ lo)
{
    size_t i = (size_t)blockIdx.x * 256 + threadIdx.x;
    float v = A[i];
    __nv_bfloat16 h = __float2bfloat16(v);
    float res = v - __bfloat162float(h);
    hi[i] = h;
    lo[i] = __float2bfloat16(res);
}

// ---------------------------------------------------------------------------
// Generic 128x128 split-bf16 mma GEMM (gi/gh): C = A @ B^T + bias
// A: Mx K, B: N x K, bf16 hi/lo. K % 64 == 0, N % 128 == 0.
// ---------------------------------------------------------------------------
#define GROW 144u
#define GTILE_BYTES (128u * GROW)
#define GSTAGE_BYTES (4u * GTILE_BYTES)
#define GSMEM_BYTES  (2u * GSTAGE_BYTES)
#define GOFF_AHI 0u
#define GOFF_ALO GTILE_BYTES
#define GOFF_BHI (2u * GTILE_BYTES)
#define GOFF_BLO (3u * GTILE_BYTES)

__device__ __forceinline__ void g_load_chunk(
    uint32_t sbase,
    const __nv_bfloat16* __restrict__ Ahi, const __nv_bfloat16* __restrict__ Alo,
    const __nv_bfloat16* __restrict__ Bhi, const __nv_bfloat16* __restrict__ Blo,
    size_t mb, size_t nb, int kc, int tid, int K)
{
    const size_t koff = (size_t)kc * 64;
    #pragma unroll
    for (int it = 0; it < 4; ++it) {
        int idx = tid + it * 256;
        int r = idx >> 3, c = idx & 7;
        uint32_t soff = (uint32_t)r * GROW + (uint32_t)c * 16u;
        CP_ASYNC16(sbase + GOFF_AHI + soff, Ahi + (mb + r) * K + koff + c * 8);
        CP_ASYNC16(sbase + GOFF_ALO + soff, Alo + (mb + r) * K + koff + c * 8);
        CP_ASYNC16(sbase + GOFF_BHI + soff, Bhi + (nb + r) * K + koff + c * 8);
        CP_ASYNC16(sbase + GOFF_BLO + soff, Blo + (nb + r) * K + koff + c * 8);
    }
}

__global__ void __launch_bounds__(256, 1) gemm_mma_bias(
    const __nv_bfloat16* __restrict__ Ahi, const __nv_bfloat16* __restrict__ Alo,
    const __nv_bfloat16* __restrict__ Bhi, const __nv_bfloat16* __restrict__ Blo,
    const float* __restrict__ bias, float* __restrict__ C,
    int N, int K)
{
    extern __shared__ char smraw[];
    const uint32_t smb = smem_u32(smraw);

    const int tid  = threadIdx.x;
    const int wid  = tid >> 5;
    const int lane = tid & 31;
    const int wm   = wid & 1;
    const int wn   = wid >> 1;
    const size_t mb = (size_t)blockIdx.x * 128;
    const size_t nb = (size_t)blockIdx.y * 128;
    const int nch = K / 64;

    const int lr = lane & 7;
    const int lg = lane >> 3;

    uint32_t aRow[4], bRow[2];
    #pragma unroll
    for (int mt = 0; mt < 4; ++mt)
        aRow[mt] = (uint32_t)(wm * 64 + mt * 16 + lr + (lg & 1) * 8) * GROW
                 + (uint32_t)((lg >> 1) * 16);
    #pragma unroll
    for (int p = 0; p < 2; ++p)
        bRow[p] = (uint32_t)(wn * 32 + p * 16 + lr + (lg >> 1) * 8) * GROW
                + (uint32_t)((lg & 1) * 16);

    float acc[4][4][4];
    #pragma unroll
    for (int mt = 0; mt < 4; ++mt)
        #pragma unroll
        for (int nt = 0; nt < 4; ++nt)
            #pragma unroll
            for (int i = 0; i < 4; ++i) acc[mt][nt][i] = 0.f;

    g_load_chunk(smb, Ahi, Alo, Bhi, Blo, mb, nb, 0, tid, K);
    CP_COMMIT();

    for (int ch = 0; ch < nch; ++ch) {
        const uint32_t st = (uint32_t)(ch & 1) * GSTAGE_BYTES;
        if (ch < nch - 1) {
            g_load_chunk(smb + ((uint32_t)((ch + 1) & 1) * GSTAGE_BYTES),
                         Ahi, Alo, Bhi, Blo, mb, nb, ch + 1, tid, K);
            CP_COMMIT();
            CP_WAIT1();
        } else {
            CP_WAIT0();
        }
        __syncthreads();

        #pragma unroll
        for (int ks = 0; ks < 4; ++ks) {
            const uint32_t kso = (uint32_t)ks * 32u;
            uint32_t ah[4][4], al[4][4];
            #pragma unroll
            for (int mt = 0; mt < 4; ++mt) {
                LDSM4(ah[mt][0], ah[mt][1], ah[mt][2], ah[mt][3], smb + st + GOFF_AHI + aRow[mt] + kso);
                LDSM4(al[mt][0], al[mt][1], al[mt][2], al[mt][3], smb + st + GOFF_ALO + aRow[mt] + kso);
            }
            uint32_t bh[4][2], bl[4][2];
            #pragma unroll
            for (int p = 0; p < 2; ++p) {
                LDSM4(bh[2 * p][0], bh[2 * p][1], bh[2 * p + 1][0], bh[2 * p + 1][1],
                      smb + st + GOFF_BHI + bRow[p] + kso);
                LDSM4(bl[2 * p][0], bl[2 * p][1], bl[2 * p + 1][0], bl[2 * p + 1][1],
                      smb + st + GOFF_BLO + bRow[p] + kso);
            }
            #pragma unroll
            for (int mt = 0; mt < 4; ++mt)
                #pragma unroll
                for (int nt = 0; nt < 4; ++nt) {
                    MMA_BF16(acc[mt][nt], ah[mt], bh[nt]);
                    MMA_BF16(acc[mt][nt], ah[mt], bl[nt]);
                    MMA_BF16(acc[mt][nt], al[mt], bh[nt]);
                }
        }
        __syncthreads();
    }

    const int rq = lane >> 2, cq = (lane & 3) * 2;
    #pragma unroll
    for (int nt = 0; nt < 4; ++nt) {
        const size_t col = nb + (size_t)wn * 32 + nt * 8 + cq;
        const float2 bv = *(const float2*)&bias[col];
        #pragma unroll
        for (int mt = 0; mt < 4; ++mt) {
            const size_t row0 = mb + (size_t)wm * 64 + mt * 16 + rq;
            float2 v0, v1;
            v0.x = acc[mt][nt][0] + bv.x;
            v0.y = acc[mt][nt][1] + bv.y;
            v1.x = acc[mt][nt][2] + bv.x;
            v1.y = acc[mt][nt][3] + bv.y;
            *(float2*)&C[row0 * N + col]       = v0;
            *(float2*)&C[(row0 + 8) * N + col] = v1;
        }
    }
}

// ---------------------------------------------------------------------------
// mma.sync vocab GEMM: K-chunk 32, 2-stage, 2 CTAs/SM.
// ---------------------------------------------------------------------------
#define VROW 80u
#define VTILE_BYTES (128u * VROW)             // 10240
#define VSTAGE_BYTES (4u * VTILE_BYTES)       // 40960
#define VSMEM_BYTES  (2u * VSTAGE_BYTES)      // 81920

#define VOFF_AHI 0u
#define VOFF_ALO VTILE_BYTES
#define VOFF_BHI (2u * VTILE_BYTES)
#define VOFF_BLO (3u * VTILE_BYTES)

__device__ __forceinline__ void v_load_chunk(
    uint32_t sbase,
    const __nv_bfloat16* __restrict__ Ahi, const __nv_bfloat16* __restrict__ Alo,
    const __nv_bfloat16* __restrict__ Bhi, const __nv_bfloat16* __restrict__ Blo,
    size_t mb, size_t nb, int kc, int tid)
{
    const size_t koff = (size_t)kc * 32;
    #pragma unroll
    for (int it = 0; it < 2; ++it) {
        int idx = tid + it * 256;              // 0..511
        int r = idx >> 2, c = idx & 3;
        uint32_t soff = (uint32_t)r * VROW + (uint32_t)c * 16u;
        CP_ASYNC16(sbase + VOFF_AHI + soff, Ahi + (mb + r) * H_ + koff + c * 8);
        CP_ASYNC16(sbase + VOFF_ALO + soff, Alo + (mb + r) * H_ + koff + c * 8);
        CP_ASYNC16(sbase + VOFF_BHI + soff, Bhi + (nb + r) * H_ + koff + c * 8);
        CP_ASYNC16(sbase + VOFF_BLO + soff, Blo + (nb + r) * H_ + koff + c * 8);
    }
}

__global__ void __launch_bounds__(256, 2) vocab_mma_kernel(
    const __nv_bfloat16* __restrict__ Ahi, const __nv_bfloat16* __restrict__ Alo,
    const __nv_bfloat16* __restrict__ Bhi, const __nv_bfloat16* __restrict__ Blo,
    const float* __restrict__ bias, float* __restrict__ C)
{
    extern __shared__ char smraw[];
    const uint32_t smb = smem_u32(smraw);

    const int tid  = threadIdx.x;
    const int wid  = tid >> 5;
    const int lane = tid & 31;
    const int wm   = wid & 1;
    const int wn   = wid >> 1;
    const size_t mb = (size_t)blockIdx.x * 128;
    const size_t nb = (size_t)blockIdx.y * 128;

    const int lr = lane & 7;
    const int lg = lane >> 3;

    uint32_t aRow[4], bRow[2];
    #pragma unroll
    for (int mt = 0; mt < 4; ++mt)
        aRow[mt] = (uint32_t)(wm * 64 + mt * 16 + lr + (lg & 1) * 8) * VROW
                 + (uint32_t)((lg >> 1) * 16);
    #pragma unroll
    for (int p = 0; p < 2; ++p)
        bRow[p] = (uint32_t)(wn * 32 + p * 16 + lr + (lg >> 1) * 8) * VROW
                + (uint32_t)((lg & 1) * 16);

    float acc[4][4][4];
    #pragma unroll
    for (int mt = 0; mt < 4; ++mt)
        #pragma unroll
        for (int nt = 0; nt < 4; ++nt)
            #pragma unroll
            for (int i = 0; i < 4; ++i) acc[mt][nt][i] = 0.f;

    v_load_chunk(smb, Ahi, Alo, Bhi, Blo, mb, nb, 0, tid);
    CP_COMMIT();

    for (int ch = 0; ch < 8; ++ch) {
        const uint32_t st = (uint32_t)(ch & 1) * VSTAGE_BYTES;
        if (ch < 7) {
            v_load_chunk(smb + ((uint32_t)((ch + 1) & 1) * VSTAGE_BYTES),
                         Ahi, Alo, Bhi, Blo, mb, nb, ch + 1, tid);
            CP_COMMIT();
            CP_WAIT1();
        } else {
            CP_WAIT0();
        }
        __syncthreads();

        #pragma unroll
        for (int ks = 0; ks < 2; ++ks) {
            const uint32_t kso = (uint32_t)ks * 32u;
            uint32_t ah[4][4], al[4][4];
            #pragma unroll
            for (int mt = 0; mt < 4; ++mt) {
                LDSM4(ah[mt][0], ah[mt][1], ah[mt][2], ah[mt][3], smb + st + VOFF_AHI + aRow[mt] + kso);
                LDSM4(al[mt][0], al[mt][1], al[mt][2], al[mt][3], smb + st + VOFF_ALO + aRow[mt] + kso);
            }
            uint32_t bh[4][2], bl[4][2];
            #pragma unroll
            for (int p = 0; p < 2; ++p) {
                LDSM4(bh[2 * p][0], bh[2 * p][1], bh[2 * p + 1][0], bh[2 * p + 1][1],
                      smb + st + VOFF_BHI + bRow[p] + kso);
                LDSM4(bl[2 * p][0], bl[2 * p][1], bl[2 * p + 1][0], bl[2 * p + 1][1],
                      smb + st + VOFF_BLO + bRow[p] + kso);
            }
            #pragma unroll
            for (int mt = 0; mt < 4; ++mt)
                #pragma unroll
                for (int nt = 0; nt < 4; ++nt) {
                    MMA_BF16(acc[mt][nt], ah[mt], bh[nt]);
                    MMA_BF16(acc[mt][nt], ah[mt], bl[nt]);
                    MMA_BF16(acc[mt][nt], al[mt], bh[nt]);
                }
        }
        __syncthreads();
    }

    const int rq = lane >> 2, cq = (lane & 3) * 2;
    #pragma unroll
    for (int nt = 0; nt < 4; ++nt) {
        const size_t col = nb + (size_t)wn * 32 + nt * 8 + cq;
        if (col < (size_t)V_) {
            const float2 bv = *(const float2*)&bias[col];
            #pragma unroll
            for (int mt = 0; mt < 4; ++mt) {
                const size_t row0 = mb + (size_t)wm * 64 + mt * 16 + rq;
                float2 v0, v1;
                v0.x = acc[mt][nt][0] + bv.x;
                v0.y = acc[mt][nt][1] + bv.y;
                v1.x = acc[mt][nt][2] + bv.x;
                v1.y = acc[mt][nt][3] + bv.y;
                *(float2*)&C[row0 * V_ + col]       = v0;
                *(float2*)&C[(row0 + 8) * V_ + col] = v1;
            }
        }
    }
}

// ---------------------------------------------------------------------------
extern "C" void kernel_launch(void* const* d_in, const int* in_sizes, int n_in,
                              void* d_out, int out_size)
{
    (void)in_sizes; (void)n_in; (void)out_size;
    const float* emb      = (const float*)d_in[0];
    const float* hidden   = (const float*)d_in[1];
    const float* inter    = (const float*)d_in[2];
    const float* W_inter  = (const float*)d_in[4];
    const float* b_inter  = (const float*)d_in[5];
    const float* W_hidden = (const float*)d_in[6];
    const float* b_hidden = (const float*)d_in[7];
    const float* W_scale  = (const float*)d_in[8];
    const float* b_scale  = (const float*)d_in[9];
    const float* W_lt1    = (const float*)d_in[10];
    const float* b_lt1    = (const float*)d_in[11];
    const float* W_ih     = (const float*)d_in[12];
    const float* W_hh     = (const float*)d_in[13];
    const float* b_ih     = (const float*)d_in[14];
    const float* b_hh     = (const float*)d_in[15];
    const float* W_out    = (const float*)d_in[16];
    const float* b_out    = (const float*)d_in[17];
    const int* user_list  = (const int*)d_in[19];
    float* out = (float*)d_out;

    cudaFuncSetAttribute(attn_mma_kernel,
                         cudaFuncAttributeMaxDynamicSharedMemorySize, AT_BYTES);
    cudaFuncSetAttribute(vocab_mma_kernel,
                         cudaFuncAttributeMaxDynamicSharedMemorySize, VSMEM_BYTES);
    cudaFuncSetAttribute(gemm_mma_bias,
                         cudaFuncAttributeMaxDynamicSharedMemorySize, GSMEM_BYTES);

    void *p_gi, *p_gh, *p_perm, *p_htp;
    void *p_bhi, *p_blo, *p_ahi, *p_alo;
    void *p_xchi, *p_xclo, *p_wihhi, *p_wihlo, *p_whhhi, *p_whhlo, *p_hidhi, *p_hidlo;
    cudaGetSymbolAddress(&p_gi, g_gi);
    cudaGetSymbolAddress(&p_gh, g_gh);
    cudaGetSymbolAddress(&p_perm, g_perm);
    cudaGetSymbolAddress(&p_htp, g_htp);
    cudaGetSymbolAddress(&p_bhi, g_b_hi);
    cudaGetSymbolAddress(&p_blo, g_b_lo);
    cudaGetSymbolAddress(&p_ahi, g_a_hi);
    cudaGetSymbolAddress(&p_alo, g_a_lo);
    cudaGetSymbolAddress(&p_xchi, g_xc_hi);
    cudaGetSymbolAddress(&p_xclo, g_xc_lo);
    cudaGetSymbolAddress(&p_wihhi, g_wih_hi);
    cudaGetSymbolAddress(&p_wihlo, g_wih_lo);
    cudaGetSymbolAddress(&p_whhhi, g_whh_hi);
    cudaGetSymbolAddress(&p_whhlo, g_whh_lo);
    cudaGetSymbolAddress(&p_hidhi, g_hid_hi);
    cudaGetSymbolAddress(&p_hidlo, g_hid_lo);

    // 0) sort + weight conversions
    sort_users_kernel<<<1, 1024>>>(user_list, (int*)p_perm);
    cvt_b_kernel<<<VPAD_, 256>>>(W_out, (__nv_bfloat16*)p_bhi, (__nv_bfloat16*)p_blo);
    cvt_a_kernel<<<(768 * 512) / 256, 256>>>(W_ih, (__nv_bfloat16*)p_wihhi, (__nv_bfloat16*)p_wihlo);
    cvt_a_kernel<<<(768 * 256) / 256, 256>>>(W_hh, (__nv_bfloat16*)p_whhhi, (__nv_bfloat16*)p_whhlo);
    cvt_a_kernel<<<(B_ * 256) / 256, 256>>>(hidden, (__nv_bfloat16*)p_hidhi, (__nv_bfloat16*)p_hidlo);

    // 1) htpart pre-kernel
    htpart_kernel<<<B_, 256>>>(hidden, W_hidden, b_hidden, W_lt1,
                               user_list, (const int*)p_perm, (float*)p_htp);

    // 2) tensor-core attention -> attn out + xcat bf16 hi/lo
    attn_mma_kernel<<<B_, 256, AT_BYTES>>>(
        inter, emb,
        W_inter, b_inter, W_scale, b_scale, W_lt1, b_lt1,
        user_list, (const int*)p_perm, (const float*)p_htp,
        out + ATTN_OFF, (__nv_bfloat16*)p_xchi, (__nv_bfloat16*)p_xclo);

    // 3) gi = xcat @ W_ih^T + b_ih  (mma, K=512)
    {
        dim3 grid(B_ / 128, 768 / 128);
        gemm_mma_bias<<<grid, 256, GSMEM_BYTES>>>(
            (const __nv_bfloat16*)p_xchi, (const __nv_bfloat16*)p_xclo,
            (const __nv_bfloat16*)p_wihhi, (const __nv_bfloat16*)p_wihlo,
            b_ih, (float*)p_gi, 768, 512);
    }
    // 4) gh = h0 @ W_hh^T + b_hh  (mma, K=256)
    {
        dim3 grid(B_ / 128, 768 / 128);
        gemm_mma_bias<<<grid, 256, GSMEM_BYTES>>>(
            (const __nv_bfloat16*)p_hidhi, (const __nv_bfloat16*)p_hidlo,
            (const __nv_bfloat16*)p_whhhi, (const __nv_bfloat16*)p_whhlo,
            b_hh, (float*)p_gh, 768, 256);
    }
    // 5) gates -> h_new
    gru_gate_kernel<<<(B_ * H_) / 256, 256>>>(
        (const float*)p_gi, (const float*)p_gh, hidden,
        out + HID_OFF, out + GRU_OFF);

    // 6) h_new -> split bf16
    cvt_a_kernel<<<(B_ * H_) / 256, 256>>>(out + HID_OFF,
                                           (__nv_bfloat16*)p_ahi,
                                           (__nv_bfloat16*)p_alo);

    // 7) output = h_new @ W_out^T + b_out  (mma, 2 CTAs/SM)
    {
        dim3 grid(B_ / 128, VPAD_ / 128);
        vocab_mma_kernel<<<grid, 256, VSMEM_BYTES>>>(
            (const __nv_bfloat16*)p_ahi, (const __nv_bfloat16*)p_alo,
            (const __nv_bfloat16*)p_bhi, (const __nv_bfloat16*)p_blo,
            b_out, out + OUT_OFF);
    }

    // 8) emb passthrough output
    cudaMemcpyAsync(out + EMB_OFF, emb, (size_t)B_ * E_ * sizeof(float),
                    cudaMemcpyDeviceToDevice, 0);
}